// round 10
// baseline (speedup 1.0000x reference)
#include <cuda_runtime.h>
#include <math.h>
#include <stdint.h>

#define BSZ   8
#define LSEQ  1024
#define DM    512
#define DI    1024
#define MROWS (BSZ*LSEQ)   /* 8192 */

/* ---------------- scratch arena (overlayed by phase) ---------------- */
#define OFF_XZ_F   0ull
#define OFF_XZ_B   16777216ull
#define OFF_XC_F   33554432ull
#define OFF_XC_B   41943040ull
#define OFF_DLT_F  50331648ull
#define OFF_DLT_B  58720256ull
#define OFF_YG_F   67108864ull
#define OFF_YG_B   75497472ull
#define OFF_XDBL_F 83886080ull
#define OFF_XDBL_B 84672512ull
/* tf32-rounded copies of GEMM inputs (pre-converted once per call) */
#define OFF_XC0    85458944ull   /* rounded X, 4194304 */
#define OFF_FIW    89653248ull
#define OFF_BIW    90701824ull
#define OFF_FXP    91750400ull
#define OFF_BXP    91848704ull
#define OFF_FDT    91947008ull
#define OFF_BDT    91979776ull
#define OFF_FOW    92012544ull
#define OFF_BOW    92536832ull
#define OFF_W1     93061120ull
#define OFF_W2     94109696ull
#define ARENA_FLOATS 95158272ull
#define OFF_OUT_F  OFF_XC_F
#define OFF_OUT_B  OFF_XC_B
#define OFF_OUT1   OFF_DLT_F
#define OFF_FFNH   OFF_XZ_F
#define OFF_FFNO   OFF_YG_F

__device__ float g_arena[ARENA_FLOATS];

__device__ __forceinline__ uint32_t f2tf32(float x){
    uint32_t r; asm("cvt.rna.tf32.f32 %0, %1;" : "=r"(r) : "f"(x)); return r;
}
__device__ __forceinline__ float rnd_tf32(float x){ return __uint_as_float(f2tf32(x)); }

__device__ __forceinline__ uint32_t smem_u32(const void* p){
    uint32_t a;
    asm("{ .reg .u64 t; cvta.to.shared.u64 t, %1; cvt.u32.u64 %0, t; }" : "=r"(a) : "l"(p));
    return a;
}
__device__ __forceinline__ void cp16(uint32_t dst, const float* src, uint32_t nbytes){
    asm volatile("cp.async.cg.shared.global [%0], [%1], 16, %2;"
                 :: "r"(dst), "l"(src), "r"(nbytes) : "memory");
}
__device__ __forceinline__ void mma_tf32(float* d, const uint32_t* a, const uint32_t* b){
    asm volatile("mma.sync.aligned.m16n8k8.row.col.f32.tf32.tf32.f32 "
                 "{%0,%1,%2,%3}, {%4,%5,%6,%7}, {%8,%9}, {%0,%1,%2,%3};"
                 : "+f"(d[0]), "+f"(d[1]), "+f"(d[2]), "+f"(d[3])
                 : "r"(a[0]), "r"(a[1]), "r"(a[2]), "r"(a[3]),
                   "r"(b[0]), "r"(b[1]));
}

/* ---------------- epilogues ---------------- */
template<int EPI, int RND>
__device__ __forceinline__ float epi_apply(float v, const float* __restrict__ bias, int n){
    float x = v;
    if (EPI != 0){
        x = v + bias[n];
        if (EPI == 2) x = 0.5f * x * (1.0f + erff(x * 0.70710678118654752f)); /* exact gelu */
        else if (EPI == 3) x = (x > 20.0f) ? x : log1pf(__expf(x));           /* softplus */
    }
    return RND ? rnd_tf32(x) : x;
}

/* ---------------- TF32 HMMA GEMM v2: C[m,n] = sum_k A[m,k] * W[n,k] ----------------
   CTA 128x128 tile, 8 warps (warp tile 64x32, 4x4 frags m16n8k8).
   K-chunks of 32, 3-stage cp.async pipeline, row-major padded smem (stride 36 floats,
   conflict-free LDS.32 fragment loads). Inputs are pre-rounded to tf32 (no cvt here).
   blockIdx.z selects the fwd/bwd pointer set. */
#define STAGES 3
#define CHUNK  32
#define SROW   36
#define STILE  (128*SROW)            /* floats per stage tile: 4608 */
#define STILE_B (STILE*4)            /* bytes: 18432 */
#define SMEM_GEMM (STAGES*STILE_B*2) /* 110592 */

template<int EPI, int RND>
__global__ __launch_bounds__(256) void tf32_gemm(
    const float* __restrict__ A0, const float* __restrict__ A1, int lda,
    const float* __restrict__ W0, const float* __restrict__ W1, int ldw,
    const float* __restrict__ bias0, const float* __restrict__ bias1,
    float* __restrict__ C0, float* __restrict__ C1, int ldc,
    int N, int K)
{
    extern __shared__ float smem[];
    const float* A    = blockIdx.z ? A1 : A0;
    const float* W    = blockIdx.z ? W1 : W0;
    const float* bias = blockIdx.z ? bias1 : bias0;
    float*       C    = blockIdx.z ? C1 : C0;

    int tid = threadIdx.x, wid = tid >> 5, lane = tid & 31;
    int wm = wid & 1, wn = wid >> 1;
    int g = lane >> 2, tig = lane & 3;
    int m0 = blockIdx.y * 128, n0 = blockIdx.x * 128;
    int nt = N - n0; if (nt > 128) nt = 128;

    /* loader: 2 threads per row, each copies 16 consecutive k (4 x cp.async 16B) */
    int r = tid >> 1, half = tid & 1;
    const float* Ag = A + (size_t)(m0 + r) * lda + half * 16;
    const float* Wg = W + (size_t)(n0 + r) * ldw + half * 16;
    uint32_t wbytes = (r < nt) ? 16u : 0u;

    uint32_t sbase = smem_u32(smem);
    uint32_t sa_dst = sbase + (uint32_t)((r * SROW + half * 16) * 4);
    uint32_t sb_dst = sa_dst + (uint32_t)(STAGES * STILE_B);

    float acc[4][4][4];
    #pragma unroll
    for (int i=0;i<4;i++)
        #pragma unroll
        for (int j=0;j<4;j++)
            #pragma unroll
            for (int q=0;q<4;q++) acc[i][j][q] = 0.f;

    int KCn = K >> 5;

    /* prologue: stages 0..STAGES-2 */
    #pragma unroll
    for (int s = 0; s < STAGES-1; s++){
        if (s < KCn){
            const float* ag = Ag + s * CHUNK;
            const float* wg = Wg + s * CHUNK;
            uint32_t da = sa_dst + s * STILE_B;
            uint32_t db = sb_dst + s * STILE_B;
            #pragma unroll
            for (int q = 0; q < 4; q++){
                cp16(da + q*16, ag + q*4, 16u);
                cp16(db + q*16, wg + q*4, wbytes);
            }
        }
        asm volatile("cp.async.commit_group;" ::: "memory");
    }

    for (int c = 0; c < KCn; c++){
        asm volatile("cp.async.wait_group 1;" ::: "memory");
        __syncthreads();
        /* issue chunk c+STAGES-1 into stage (c+STAGES-1)%STAGES (== (c-1)%STAGES buffer) */
        int cn = c + STAGES - 1;
        if (cn < KCn){
            int st = cn % STAGES;
            const float* ag = Ag + cn * CHUNK;
            const float* wg = Wg + cn * CHUNK;
            uint32_t da = sa_dst + st * STILE_B;
            uint32_t db = sb_dst + st * STILE_B;
            #pragma unroll
            for (int q = 0; q < 4; q++){
                cp16(da + q*16, ag + q*4, 16u);
                cp16(db + q*16, wg + q*4, wbytes);
            }
        }
        asm volatile("cp.async.commit_group;" ::: "memory");

        /* compute stage c%STAGES */
        const float* sAs = smem + (c % STAGES) * STILE;
        const float* sBs = smem + STAGES * STILE + (c % STAGES) * STILE;
        #pragma unroll
        for (int s = 0; s < 4; s++){
            int k = s*8 + tig;
            uint32_t af[4][4], bf[4][2];
            #pragma unroll
            for (int f = 0; f < 4; f++){
                const float* p = sAs + (wm*64 + f*16 + g) * SROW + k;
                af[f][0] = __float_as_uint(p[0]);
                af[f][1] = __float_as_uint(p[8*SROW]);
                af[f][2] = __float_as_uint(p[4]);
                af[f][3] = __float_as_uint(p[8*SROW + 4]);
            }
            #pragma unroll
            for (int j = 0; j < 4; j++){
                const float* p = sBs + (wn*32 + j*8 + g) * SROW + k;
                bf[j][0] = __float_as_uint(p[0]);
                bf[j][1] = __float_as_uint(p[4]);
            }
            #pragma unroll
            for (int f = 0; f < 4; f++)
                #pragma unroll
                for (int j = 0; j < 4; j++)
                    mma_tf32(acc[f][j], af[f], bf[j]);
        }
    }

    /* epilogue: c0,c1 = (row, 2*tig..+1); c2,c3 = (row+8, ...) */
    #pragma unroll
    for (int f = 0; f < 4; f++){
        int row = m0 + wm*64 + f*16 + g;
        #pragma unroll
        for (int j = 0; j < 4; j++){
            int nb = n0 + wn*32 + j*8;
            if (nb < N){
                int cn = nb + tig*2;
                float2 v;
                v.x = epi_apply<EPI,RND>(acc[f][j][0], bias, cn);
                v.y = epi_apply<EPI,RND>(acc[f][j][1], bias, cn+1);
                *(float2*)&C[(size_t)row * ldc + cn] = v;
                v.x = epi_apply<EPI,RND>(acc[f][j][2], bias, cn);
                v.y = epi_apply<EPI,RND>(acc[f][j][3], bias, cn+1);
                *(float2*)&C[(size_t)(row+8) * ldc + cn] = v;
            }
        }
    }
}

/* ---------------- tf32 pre-rounding copy (float4) ---------------- */
__global__ __launch_bounds__(256) void cvt_tf32_vec(const float* __restrict__ src,
                                                    float* __restrict__ dst, int n4){
    int i = blockIdx.x * 256 + threadIdx.x;
    if (i < n4){
        float4 v = ((const float4*)src)[i];
        v.x = rnd_tf32(v.x); v.y = rnd_tf32(v.y);
        v.z = rnd_tf32(v.z); v.w = rnd_tf32(v.w);
        ((float4*)dst)[i] = v;
    }
}

/* ---------------- causal / anti-causal depthwise conv + SiLU (tf32-rounded out) ---- */
__global__ __launch_bounds__(256) void conv_silu(
    const float* __restrict__ xzf, const float* __restrict__ xzb,
    const float* __restrict__ fw, const float* __restrict__ fbias,
    const float* __restrict__ bw, const float* __restrict__ bbias,
    float* __restrict__ xcf, float* __restrict__ xcb)
{
    int lin = blockIdx.x * 256 + threadIdx.x;
    int ch = lin & (DI-1);
    int t  = lin >> 10;
    int b  = blockIdx.y;
    int dir = blockIdx.z;
    const float* __restrict__ xin = dir ? xzb : xzf;
    const float* __restrict__ cw  = dir ? bw : fw;
    const float* __restrict__ cb  = dir ? bbias : fbias;
    float* out = dir ? xcb : xcf;

    float acc = __ldg(&cb[ch]);
    float w0 = __ldg(&cw[ch*4+0]), w1 = __ldg(&cw[ch*4+1]);
    float w2 = __ldg(&cw[ch*4+2]), w3 = __ldg(&cw[ch*4+3]);
    size_t base = ((size_t)b * LSEQ) * (2*DI) + ch;
    if (dir == 0){
        if (t-3 >= 0) acc = fmaf(w0, __ldg(&xin[base + (size_t)(t-3)*(2*DI)]), acc);
        if (t-2 >= 0) acc = fmaf(w1, __ldg(&xin[base + (size_t)(t-2)*(2*DI)]), acc);
        if (t-1 >= 0) acc = fmaf(w2, __ldg(&xin[base + (size_t)(t-1)*(2*DI)]), acc);
        acc = fmaf(w3, __ldg(&xin[base + (size_t)t*(2*DI)]), acc);
    } else {
        if (t+3 < LSEQ) acc = fmaf(w0, __ldg(&xin[base + (size_t)(t+3)*(2*DI)]), acc);
        if (t+2 < LSEQ) acc = fmaf(w1, __ldg(&xin[base + (size_t)(t+2)*(2*DI)]), acc);
        if (t+1 < LSEQ) acc = fmaf(w2, __ldg(&xin[base + (size_t)(t+1)*(2*DI)]), acc);
        acc = fmaf(w3, __ldg(&xin[base + (size_t)t*(2*DI)]), acc);
    }
    out[((size_t)b*LSEQ + t)*DI + ch] = rnd_tf32(acc / (1.0f + __expf(-acc)));
}

/* ---------------- selective scan + gating (yg tf32-rounded for out_proj) ---------- */
__global__ __launch_bounds__(128) void scan_gate(
    const float* __restrict__ delta_f, const float* __restrict__ delta_b,
    const float* __restrict__ xc_f,    const float* __restrict__ xc_b,
    const float* __restrict__ xdbl_f,  const float* __restrict__ xdbl_b,
    const float* __restrict__ xz_f,    const float* __restrict__ xz_b,
    const float* __restrict__ Alog_f,  const float* __restrict__ Alog_b,
    const float* __restrict__ D_f,     const float* __restrict__ D_b,
    float* __restrict__ yg_f, float* __restrict__ yg_b)
{
    int dir = blockIdx.z;
    const float* __restrict__ delta = dir ? delta_b : delta_f;
    const float* __restrict__ xc    = dir ? xc_b    : xc_f;
    const float* __restrict__ xdbl  = dir ? xdbl_b  : xdbl_f;
    const float* __restrict__ xz    = dir ? xz_b    : xz_f;
    const float* __restrict__ Alog  = dir ? Alog_b  : Alog_f;
    const float* __restrict__ Dp    = dir ? D_b     : D_f;
    float* yg                       = dir ? yg_b    : yg_f;

    int ch = blockIdx.x * 128 + threadIdx.x;
    int b  = blockIdx.y;

    float Aev[32];
    #pragma unroll
    for (int n=0;n<32;n++) Aev[n] = -__expf(__ldg(&Alog[ch*32 + n]));
    float Dch = __ldg(&Dp[ch]);
    float h[32];
    #pragma unroll
    for (int n=0;n<32;n++) h[n] = 0.f;

    int t0 = dir ? (LSEQ-1) : 0;
    size_t row0 = (size_t)b*LSEQ + t0;
    float d  = __ldg(&delta[row0*DI + ch]);
    float u  = __ldg(&xc[row0*DI + ch]);
    float zz = __ldg(&xz[row0*(2*DI) + DI + ch]);

    for (int s=0;s<LSEQ;s++){
        int t = dir ? (LSEQ-1 - s) : s;
        float dn=0.f, un=0.f, zn=0.f;
        if (s+1 < LSEQ){
            int tn = dir ? (t-1) : (t+1);
            size_t rn = (size_t)b*LSEQ + tn;
            dn = __ldg(&delta[rn*DI + ch]);
            un = __ldg(&xc[rn*DI + ch]);
            zn = __ldg(&xz[rn*(2*DI) + DI + ch]);
        }
        size_t row = (size_t)b*LSEQ + t;
        const float4* Bp = (const float4*)(xdbl + row*96 + 32);
        const float4* Cp = (const float4*)(xdbl + row*96 + 64);
        float du = d * u;
        float y = 0.f;
        #pragma unroll
        for (int q=0;q<8;q++){
            float4 B4 = __ldg(&Bp[q]);
            float4 C4 = __ldg(&Cp[q]);
            int n = q*4;
            float dA;
            dA = __expf(d*Aev[n+0]); h[n+0] = fmaf(dA, h[n+0], du*B4.x); y = fmaf(h[n+0], C4.x, y);
            dA = __expf(d*Aev[n+1]); h[n+1] = fmaf(dA, h[n+1], du*B4.y); y = fmaf(h[n+1], C4.y, y);
            dA = __expf(d*Aev[n+2]); h[n+2] = fmaf(dA, h[n+2], du*B4.z); y = fmaf(h[n+2], C4.z, y);
            dA = __expf(d*Aev[n+3]); h[n+3] = fmaf(dA, h[n+3], du*B4.w); y = fmaf(h[n+3], C4.w, y);
        }
        float yv = fmaf(u, Dch, y);
        float sz = zz / (1.0f + __expf(-zz));
        yg[row*DI + ch] = rnd_tf32(yv * sz);
        d = dn; u = un; zz = zn;
    }
}

/* ---------------- layernorm helpers ---------------- */
__device__ __forceinline__ float block_sum128(float v, float* sh){
    #pragma unroll
    for (int o=16;o>0;o>>=1) v += __shfl_xor_sync(0xffffffffu, v, o);
    if ((threadIdx.x & 31) == 0) sh[threadIdx.x >> 5] = v;
    __syncthreads();
    float r = sh[0] + sh[1] + sh[2] + sh[3];
    __syncthreads();
    return r;
}

/* out1 = rnd_tf32(LN(hf*pw0 + hb*pw1 + pb + x)) — feeds FFN GEMM */
__global__ __launch_bounds__(128) void combine_ln(
    const float* __restrict__ of, const float* __restrict__ ob, const float* __restrict__ x,
    const float* __restrict__ pw, const float* __restrict__ pb,
    const float* __restrict__ g, const float* __restrict__ be, float* __restrict__ out)
{
    __shared__ float sh[4];
    size_t m = blockIdx.x;
    float w0 = __ldg(&pw[0]), w1 = __ldg(&pw[1]), b0 = __ldg(&pb[0]);
    float v[4]; float s = 0.f;
    #pragma unroll
    for (int i=0;i<4;i++){
        int n = threadIdx.x + i*128;
        size_t idx = m*DM + n;
        float val = fmaf(of[idx], w0, fmaf(ob[idx], w1, b0 + x[idx]));
        v[i] = val; s += val;
    }
    float mu = block_sum128(s, sh) * (1.f/(float)DM);
    float s2 = 0.f;
    #pragma unroll
    for (int i=0;i<4;i++){ float dd = v[i]-mu; s2 = fmaf(dd,dd,s2); }
    float inv = rsqrtf(block_sum128(s2, sh)*(1.f/(float)DM) + 1e-12f);
    #pragma unroll
    for (int i=0;i<4;i++){
        int n = threadIdx.x + i*128;
        out[m*DM + n] = rnd_tf32(fmaf((v[i]-mu)*inv, g[n], be[n]));
    }
}

__global__ __launch_bounds__(128) void add_ln(
    const float* __restrict__ a, const float* __restrict__ r,
    const float* __restrict__ g, const float* __restrict__ be, float* __restrict__ out)
{
    __shared__ float sh[4];
    size_t m = blockIdx.x;
    float v[4]; float s = 0.f;
    #pragma unroll
    for (int i=0;i<4;i++){
        int n = threadIdx.x + i*128;
        size_t idx = m*DM + n;
        float val = a[idx] + r[idx];
        v[i] = val; s += val;
    }
    float mu = block_sum128(s, sh) * (1.f/(float)DM);
    float s2 = 0.f;
    #pragma unroll
    for (int i=0;i<4;i++){ float dd = v[i]-mu; s2 = fmaf(dd,dd,s2); }
    float inv = rsqrtf(block_sum128(s2, sh)*(1.f/(float)DM) + 1e-12f);
    #pragma unroll
    for (int i=0;i<4;i++){
        int n = threadIdx.x + i*128;
        out[m*DM + n] = fmaf((v[i]-mu)*inv, g[n], be[n]);
    }
}

/* ---------------- eager init: commit module pre-main + smem attrs ---------------- */
namespace {
struct EagerInit {
    float* base;
    EagerInit() : base(nullptr) {
        void* p = nullptr;
        cudaGetSymbolAddress(&p, g_arena);
        base = (float*)p;
        cudaFuncSetAttribute(tf32_gemm<0,0>, cudaFuncAttributeMaxDynamicSharedMemorySize, SMEM_GEMM);
        cudaFuncSetAttribute(tf32_gemm<0,1>, cudaFuncAttributeMaxDynamicSharedMemorySize, SMEM_GEMM);
        cudaFuncSetAttribute(tf32_gemm<1,0>, cudaFuncAttributeMaxDynamicSharedMemorySize, SMEM_GEMM);
        cudaFuncSetAttribute(tf32_gemm<2,1>, cudaFuncAttributeMaxDynamicSharedMemorySize, SMEM_GEMM);
        cudaFuncSetAttribute(tf32_gemm<3,0>, cudaFuncAttributeMaxDynamicSharedMemorySize, SMEM_GEMM);
    }
};
EagerInit g_eager;
}

/* ---------------- host ---------------- */
static inline void cvt(const float* s, float* d, int n){
    cvt_tf32_vec<<<(n/4 + 255)/256, 256>>>(s, d, n/4);
}

extern "C" void kernel_launch(void* const* d_in, const int* in_sizes, int n_in,
                              void* d_out, int out_size)
{
    const float* X        = (const float*)d_in[0];
    /* d_in[1] = lengths (unused by the reference) */
    const float* f_in_w   = (const float*)d_in[2];
    const float* f_conv_w = (const float*)d_in[3];
    const float* f_conv_b = (const float*)d_in[4];
    const float* f_xproj  = (const float*)d_in[5];
    const float* f_dt_w   = (const float*)d_in[6];
    const float* f_dt_b   = (const float*)d_in[7];
    const float* f_A_log  = (const float*)d_in[8];
    const float* f_D      = (const float*)d_in[9];
    const float* f_out_w  = (const float*)d_in[10];
    const float* b_in_w   = (const float*)d_in[11];
    const float* b_conv_w = (const float*)d_in[12];
    const float* b_conv_b = (const float*)d_in[13];
    const float* b_xproj  = (const float*)d_in[14];
    const float* b_dt_w   = (const float*)d_in[15];
    const float* b_dt_b   = (const float*)d_in[16];
    const float* b_A_log  = (const float*)d_in[17];
    const float* b_D      = (const float*)d_in[18];
    const float* b_out_w  = (const float*)d_in[19];
    const float* proj_w   = (const float*)d_in[20];
    const float* proj_b   = (const float*)d_in[21];
    const float* ln_g     = (const float*)d_in[22];
    const float* ln_b     = (const float*)d_in[23];
    const float* ffn_w1   = (const float*)d_in[24];
    const float* ffn_b1   = (const float*)d_in[25];
    const float* ffn_w2   = (const float*)d_in[26];
    const float* ffn_b2   = (const float*)d_in[27];
    const float* ffn_ln_g = (const float*)d_in[28];
    const float* ffn_ln_b = (const float*)d_in[29];

    float* base = g_eager.base;
    if (!base){ void* p = nullptr; cudaGetSymbolAddress(&p, g_arena); base = (float*)p; }

    float* xz_f   = base + OFF_XZ_F;
    float* xz_b   = base + OFF_XZ_B;
    float* xc_f   = base + OFF_XC_F;
    float* xc_b   = base + OFF_XC_B;
    float* xdbl_f = base + OFF_XDBL_F;
    float* xdbl_b = base + OFF_XDBL_B;
    float* dlt_f  = base + OFF_DLT_F;
    float* dlt_b  = base + OFF_DLT_B;
    float* yg_f   = base + OFF_YG_F;
    float* yg_b   = base + OFF_YG_B;
    float* out_f  = base + OFF_OUT_F;
    float* out_b  = base + OFF_OUT_B;
    float* out1   = base + OFF_OUT1;
    float* ffnh   = base + OFF_FFNH;
    float* ffno   = base + OFF_FFNO;
    float* Xc     = base + OFF_XC0;
    float* fiw    = base + OFF_FIW;
    float* biw    = base + OFF_BIW;
    float* fxp    = base + OFF_FXP;
    float* bxp    = base + OFF_BXP;
    float* fdt    = base + OFF_FDT;
    float* bdt    = base + OFF_BDT;
    float* fow    = base + OFF_FOW;
    float* bow    = base + OFF_BOW;
    float* w1c    = base + OFF_W1;
    float* w2c    = base + OFF_W2;
    float* OUT    = (float*)d_out;

    /* 0) pre-round all GEMM inputs to tf32 */
    cvt(X, Xc, MROWS*DM);
    cvt(f_in_w, fiw, 2*DI*DM);   cvt(b_in_w, biw, 2*DI*DM);
    cvt(f_xproj, fxp, 96*DI);    cvt(b_xproj, bxp, 96*DI);
    cvt(f_dt_w, fdt, DI*32);     cvt(b_dt_w, bdt, DI*32);
    cvt(f_out_w, fow, DM*DI);    cvt(b_out_w, bow, DM*DI);
    cvt(ffn_w1, w1c, 4*DM*DM);   cvt(ffn_w2, w2c, DM*4*DM);

    /* 1) in_proj both dirs: xz = Xc @ in_w^T  (N=2048, K=512) */
    tf32_gemm<0,0><<<dim3(16,64,2),256,SMEM_GEMM>>>(Xc, Xc, DM, fiw, biw, DM,
                                                    nullptr, nullptr, xz_f, xz_b, 2*DI,
                                                    2*DI, DM);

    /* 2) depthwise conv + silu (xc rounded for GEMM3) */
    conv_silu<<<dim3((LSEQ*DI)/256, BSZ, 2),256>>>(xz_f, xz_b,
                                                   f_conv_w, f_conv_b, b_conv_w, b_conv_b,
                                                   xc_f, xc_b);

    /* 3) x_dbl = xc @ xproj^T  (N=96, K=1024); output rounded (feeds GEMM4 + scan) */
    tf32_gemm<0,1><<<dim3(1,64,2),256,SMEM_GEMM>>>(xc_f, xc_b, DI, fxp, bxp, DI,
                                                   nullptr, nullptr, xdbl_f, xdbl_b, 96,
                                                   96, DI);

    /* 4) delta = softplus(dt @ dt_w^T + dt_b)  (N=1024, K=32, A=xdbl lda=96) */
    tf32_gemm<3,0><<<dim3(8,64,2),256,SMEM_GEMM>>>(xdbl_f, xdbl_b, 96, fdt, bdt, 32,
                                                   f_dt_b, b_dt_b, dlt_f, dlt_b, DI,
                                                   DI, 32);

    /* 5) selective scan + u*D + silu(z) gate (yg rounded for GEMM6) */
    scan_gate<<<dim3(DI/128, BSZ, 2),128>>>(dlt_f, dlt_b, xc_f, xc_b,
                                            xdbl_f, xdbl_b, xz_f, xz_b,
                                            f_A_log, b_A_log, f_D, b_D,
                                            yg_f, yg_b);

    /* 6) out_proj: yg @ out_w^T  (N=512, K=1024); overlays dead xc */
    tf32_gemm<0,0><<<dim3(4,64,2),256,SMEM_GEMM>>>(yg_f, yg_b, DI, fow, bow, DI,
                                                   nullptr, nullptr, out_f, out_b, DM,
                                                   DM, DI);

    /* 7) out1 = rnd(LN(hf*pw0 + hb*pw1 + pb + x)); overlays dead delta */
    combine_ln<<<MROWS,128>>>(out_f, out_b, X, proj_w, proj_b, ln_g, ln_b, out1);

    /* 8) FFN up + exact gelu (rounded, feeds GEMM9)  (N=2048, K=512); overlays dead xz */
    tf32_gemm<2,1><<<dim3(16,64,1),256,SMEM_GEMM>>>(out1, out1, DM, w1c, w1c, DM,
                                                    ffn_b1, ffn_b1, ffnh, ffnh, 4*DM,
                                                    4*DM, DM);

    /* 9) FFN down + bias  (N=512, K=2048); overlays dead yg */
    tf32_gemm<1,0><<<dim3(4,64,1),256,SMEM_GEMM>>>(ffnh, ffnh, 4*DM, w2c, w2c, 4*DM,
                                                   ffn_b2, ffn_b2, ffno, ffno, DM,
                                                   DM, 4*DM);

    /* 10) final = LN(ffn_out + out1) */
    add_ln<<<MROWS,128>>>(ffno, out1, ffn_ln_g, ffn_ln_b, OUT);
}

// round 14
// speedup vs baseline: 1.2694x; 1.2694x over previous
#include <cuda_runtime.h>
#include <math.h>
#include <stdint.h>

#define BSZ   8
#define LSEQ  1024
#define DM    512
#define DI    1024
#define MROWS (BSZ*LSEQ)   /* 8192 */

/* ---------------- arena: offsets in units of 1M floats (total 96MF = 384MB) ------ */
#define MF 1048576ull
#define OFF_XZ_F   (0*MF)
#define OFF_XZ_B   (16*MF)
#define OFF_XC_F   (32*MF)
#define OFF_XC_B   (40*MF)
#define OFF_DLT_F  (48*MF)
#define OFF_DLT_B  (56*MF)
#define OFF_XDBL_F (64*MF)
#define OFF_XDBL_B (65*MF)
#define OFF_XCP_F  (66*MF)
#define OFF_XCP_B  (74*MF)
#define OFF_XP     (82*MF)
#define OFF_FIWP   (86*MF)
#define OFF_BIWP   (87*MF)
#define OFF_FXPP   (88*MF)
#define OFF_BXPP   (89*MF)
#define OFF_FDTP   (90*MF)
#define OFF_BDTP   (91*MF)
#define OFF_FOWP   (92*MF)
#define OFF_BOWP   (93*MF)
#define OFF_W1P    (94*MF)
#define OFF_W2P    (95*MF)
#define ARENA_FLOATS (96*MF)
/* overlays (lifetimes disjoint):
   ygp_f/b  -> xcp_f/b  (xcp dead after GEMM3; scan reads row-major xc)
   dtap_f/b -> Xp       (Xp dead after GEMM1)
   out_f=0, out_b=4, out1=8, out1p=12, ffnhp=16, ffno=32   (xz/xc dead after scan) */
#define OFF_YGP_F  OFF_XCP_F
#define OFF_YGP_B  OFF_XCP_B
#define OFF_DTAP_F (82*MF)
#define OFF_DTAP_B (83*MF)
#define OFF_OUT_F  (0*MF)
#define OFF_OUT_B  (4*MF)
#define OFF_OUT1   (8*MF)
#define OFF_OUT1P  (12*MF)
#define OFF_FFNHP  (16*MF)
#define OFF_FFNO   (32*MF)

__device__ float g_arena[ARENA_FLOATS];

__device__ __forceinline__ uint32_t f2tf32(float x){
    uint32_t r; asm("cvt.rna.tf32.f32 %0, %1;" : "=r"(r) : "f"(x)); return r;
}
__device__ __forceinline__ float rnd_tf32(float x){ return __uint_as_float(f2tf32(x)); }

__device__ __forceinline__ uint32_t smem_u32(const void* p){
    uint32_t a;
    asm("{ .reg .u64 t; cvta.to.shared.u64 t, %1; cvt.u32.u64 %0, t; }" : "=r"(a) : "l"(p));
    return a;
}
__device__ __forceinline__ void cp16(uint32_t dst, const float* src){
    asm volatile("cp.async.cg.shared.global [%0], [%1], 16;"
                 :: "r"(dst), "l"(src) : "memory");
}
__device__ __forceinline__ void mma_tf32(float* d, const uint32_t* a, const uint32_t* b){
    asm volatile("mma.sync.aligned.m16n8k8.row.col.f32.tf32.tf32.f32 "
                 "{%0,%1,%2,%3}, {%4,%5,%6,%7}, {%8,%9}, {%0,%1,%2,%3};"
                 : "+f"(d[0]), "+f"(d[1]), "+f"(d[2]), "+f"(d[3])
                 : "r"(a[0]), "r"(a[1]), "r"(a[2]), "r"(a[3]),
                   "r"(b[0]), "r"(b[1]));
}

/* permuted A-layout offset for element (m,k); nK8 = K/8.
   word order per lane: w0=(g,tig) w1=(g+8,tig) w2=(g,tig+4) w3=(g+8,tig+4) */
__device__ __forceinline__ size_t perm_off(int m, int k, int nK8){
    int mt = m>>7, mr = m&127;
    int fb = mr>>4, r16 = mr&15;
    int kc = k>>3, kr = k&7;
    return ((size_t)(mt*nK8 + kc)*8 + fb)*128
         + (size_t)((((r16&7)<<2) + (kr&3))<<2) + (r16>>3) + ((kr>>2)<<1);
}

/* ---------------- epilogues ---------------- */
template<int EPI, int RND>
__device__ __forceinline__ float epi_apply(float v, const float* __restrict__ bias, int n){
    float x = v;
    if (EPI != 0){
        x = v + bias[n];
        if (EPI == 2) x = 0.5f * x * (1.0f + erff(x * 0.70710678118654752f)); /* exact gelu */
        else if (EPI == 3) x = (x > 20.0f) ? x : log1pf(__expf(x));           /* softplus */
    }
    return RND ? rnd_tf32(x) : x;
}

/* ---------------- permute kernels (inputs -> fragment-ordered tf32) ---------------- */
/* B layout: ((ntile*nK8+kc)*16 + jb)*64 + (g*4+tig)*2 + w ; element: n=ntile*128+jb*8+g,
   k=kc*8+w*4+tig.  Index bit fields: w=bit0, lane=bits1-5, jb=bits6-9, blk=bits10+. */
__global__ __launch_bounds__(256) void permB(const float* __restrict__ src,
                                             float* __restrict__ dst,
                                             int N, int K, int total){
    int idx = blockIdx.x*256 + threadIdx.x;
    if (idx >= total) return;
    int w = idx & 1, lane = (idx>>1)&31, jb = (idx>>6)&15;
    int blk = idx>>10;
    int nK8 = K>>3;
    int kc = blk % nK8, ntile = blk / nK8;
    int n = ntile*128 + jb*8 + (lane>>2);
    int k = kc*8 + w*4 + (lane&3);
    dst[idx] = (n < N) ? rnd_tf32(src[(size_t)n*K + k]) : 0.f;
}
/* A layout: ((mt*nK8+kc)*8 + fb)*128 + (g*4+tig)*4 + w
   bit fields: w=bits0-1, lane=bits2-6, fb=bits7-9, blk=bits10+ */
__global__ __launch_bounds__(256) void permA(const float* __restrict__ src,
                                             float* __restrict__ dst,
                                             int lda, int K, int total){
    int idx = blockIdx.x*256 + threadIdx.x;
    if (idx >= total) return;
    int w = idx & 3, lane = (idx>>2)&31, fb = (idx>>7)&7;
    int blk = idx>>10;
    int nK8 = K>>3;
    int kc = blk % nK8, mt = blk / nK8;
    int m = mt*128 + fb*16 + (w&1)*8 + (lane>>2);
    int k = kc*8 + (w>>1)*4 + (lane&3);
    dst[idx] = rnd_tf32(src[(size_t)m*lda + k]);
}

/* ---------------- TF32 HMMA GEMM v3 on pre-permuted operands ----------------
   C[m,n] = sum_k A[m,k]*W[n,k].  CTA 128x128, 4 warps (warp tile 64x64, 4x8 frags).
   K-chunks of 32: cp.async identity copy of 16KB A + 16KB B, 2-stage.
   OUTP=1: store C permuted (A-layout for the NEXT gemm, Kdim nK8o). */
#define MM_SMEM 65536

template<int EPI, int RND, int OUTP>
__global__ __launch_bounds__(128) void mm_perm(
    const float* __restrict__ A0, const float* __restrict__ A1,
    const float* __restrict__ B0, const float* __restrict__ B1,
    const float* __restrict__ bias0, const float* __restrict__ bias1,
    float* __restrict__ C0, float* __restrict__ C1, int ldc,
    int N, int K, int nK8o)
{
    extern __shared__ float smem[];   /* [A: 2x4096][B: 2x4096] floats */
    const float* A    = blockIdx.z ? A1 : A0;
    const float* B    = blockIdx.z ? B1 : B0;
    const float* bias = blockIdx.z ? bias1 : bias0;
    float*       C    = blockIdx.z ? C1 : C0;

    int tid = threadIdx.x, wid = tid>>5, lane = tid&31;
    int wm = wid & 1, wn = wid >> 1;
    int g = lane>>2, tig = lane&3;
    int nK8 = K>>3;
    int KC  = K>>5;

    const float* Ach = A + ((size_t)blockIdx.y * nK8) * 1024;
    const float* Bch = B + ((size_t)blockIdx.x * nK8) * 1024;

    uint32_t sbase = smem_u32(smem);
    uint32_t sa_d = sbase + tid*128;            /* + stage*16384 */
    uint32_t sb_d = sbase + 32768 + tid*128;

    float acc[4][8][4];
    #pragma unroll
    for (int f=0;f<4;f++)
        #pragma unroll
        for (int j=0;j<8;j++)
            #pragma unroll
            for (int q=0;q<4;q++) acc[f][j][q] = 0.f;

    /* prologue: chunk 0 -> stage 0 (identity copy, 128B per thread per operand) */
    #pragma unroll
    for (int q=0;q<8;q++){
        cp16(sa_d + q*16, Ach + tid*32 + q*4);
        cp16(sb_d + q*16, Bch + tid*32 + q*4);
    }
    asm volatile("cp.async.commit_group;" ::: "memory");

    for (int c=0;c<KC;c++){
        asm volatile("cp.async.wait_group 0;" ::: "memory");
        __syncthreads();
        if (c+1 < KC){
            int st = (c+1)&1;
            const float* ag = Ach + (size_t)(c+1)*4096;
            const float* bg = Bch + (size_t)(c+1)*4096;
            uint32_t da = sa_d + st*16384;
            uint32_t db = sb_d + st*16384;
            #pragma unroll
            for (int q=0;q<8;q++){
                cp16(da + q*16, ag + tid*32 + q*4);
                cp16(db + q*16, bg + tid*32 + q*4);
            }
        }
        asm volatile("cp.async.commit_group;" ::: "memory");

        const float* sAs = smem + (c&1)*4096;
        const float* sBs = smem + 8192 + (c&1)*4096;
        #pragma unroll
        for (int s=0;s<4;s++){
            uint32_t af[4][4], bf[8][2];
            #pragma unroll
            for (int f=0;f<4;f++)
                *(uint4*)af[f] = *(const uint4*)&sAs[s*1024 + (wm*4+f)*128 + lane*4];
            #pragma unroll
            for (int j=0;j<8;j++)
                *(uint2*)bf[j] = *(const uint2*)&sBs[s*1024 + (wn*8+j)*64 + lane*2];
            #pragma unroll
            for (int f=0;f<4;f++)
                #pragma unroll
                for (int j=0;j<8;j++)
                    mma_tf32(acc[f][j], af[f], bf[j]);
        }
    }

    /* epilogue */
    #pragma unroll
    for (int f=0;f<4;f++){
        int row = blockIdx.y*128 + wm*64 + f*16 + g;
        #pragma unroll
        for (int j=0;j<8;j++){
            int nb = blockIdx.x*128 + wn*64 + j*8;
            int cn = nb + tig*2;
            if (!OUTP){
                if (nb < N){
                    float2 v;
                    v.x = epi_apply<EPI,RND>(acc[f][j][0], bias, cn);
                    v.y = epi_apply<EPI,RND>(acc[f][j][1], bias, cn+1);
                    *(float2*)&C[(size_t)row * ldc + cn] = v;
                    v.x = epi_apply<EPI,RND>(acc[f][j][2], bias, cn);
                    v.y = epi_apply<EPI,RND>(acc[f][j][3], bias, cn+1);
                    *(float2*)&C[(size_t)(row+8) * ldc + cn] = v;
                }
            } else {
                #pragma unroll
                for (int q=0;q<4;q++){
                    int m = row + (q>>1)*8;
                    int k = cn + (q&1);
                    C[perm_off(m, k, nK8o)] = epi_apply<EPI,RND>(acc[f][j][q], bias, k);
                }
            }
        }
    }
}

/* ---------------- conv + SiLU: writes xc (row-major, scan) AND xcp (permuted) ---- */
__global__ __launch_bounds__(256) void conv_silu(
    const float* __restrict__ xzf, const float* __restrict__ xzb,
    const float* __restrict__ fw, const float* __restrict__ fbias,
    const float* __restrict__ bw, const float* __restrict__ bbias,
    float* __restrict__ xcf, float* __restrict__ xcb,
    float* __restrict__ xcpf, float* __restrict__ xcpb)
{
    int lin = blockIdx.x * 256 + threadIdx.x;
    int ch = lin & (DI-1);
    int t  = lin >> 10;
    int b  = blockIdx.y;
    int dir = blockIdx.z;
    const float* __restrict__ xin = dir ? xzb : xzf;
    const float* __restrict__ cw  = dir ? bw : fw;
    const float* __restrict__ cb  = dir ? bbias : fbias;
    float* out  = dir ? xcb : xcf;
    float* outp = dir ? xcpb : xcpf;

    float acc = __ldg(&cb[ch]);
    float w0 = __ldg(&cw[ch*4+0]), w1 = __ldg(&cw[ch*4+1]);
    float w2 = __ldg(&cw[ch*4+2]), w3 = __ldg(&cw[ch*4+3]);
    size_t base = ((size_t)b * LSEQ) * (2*DI) + ch;
    if (dir == 0){
        if (t-3 >= 0) acc = fmaf(w0, __ldg(&xin[base + (size_t)(t-3)*(2*DI)]), acc);
        if (t-2 >= 0) acc = fmaf(w1, __ldg(&xin[base + (size_t)(t-2)*(2*DI)]), acc);
        if (t-1 >= 0) acc = fmaf(w2, __ldg(&xin[base + (size_t)(t-1)*(2*DI)]), acc);
        acc = fmaf(w3, __ldg(&xin[base + (size_t)t*(2*DI)]), acc);
    } else {
        if (t+3 < LSEQ) acc = fmaf(w0, __ldg(&xin[base + (size_t)(t+3)*(2*DI)]), acc);
        if (t+2 < LSEQ) acc = fmaf(w1, __ldg(&xin[base + (size_t)(t+2)*(2*DI)]), acc);
        if (t+1 < LSEQ) acc = fmaf(w2, __ldg(&xin[base + (size_t)(t+1)*(2*DI)]), acc);
        acc = fmaf(w3, __ldg(&xin[base + (size_t)t*(2*DI)]), acc);
    }
    float v = rnd_tf32(acc / (1.0f + __expf(-acc)));
    int m = b*LSEQ + t;
    out[(size_t)m*DI + ch] = v;
    outp[perm_off(m, ch, DI/8)] = v;
}

/* ---------------- selective scan + gating: writes ygp (permuted only) ---------- */
__global__ __launch_bounds__(128) void scan_gate(
    const float* __restrict__ delta_f, const float* __restrict__ delta_b,
    const float* __restrict__ xc_f,    const float* __restrict__ xc_b,
    const float* __restrict__ xdbl_f,  const float* __restrict__ xdbl_b,
    const float* __restrict__ xz_f,    const float* __restrict__ xz_b,
    const float* __restrict__ Alog_f,  const float* __restrict__ Alog_b,
    const float* __restrict__ D_f,     const float* __restrict__ D_b,
    float* __restrict__ ygp_f, float* __restrict__ ygp_b)
{
    int dir = blockIdx.z;
    const float* __restrict__ delta = dir ? delta_b : delta_f;
    const float* __restrict__ xc    = dir ? xc_b    : xc_f;
    const float* __restrict__ xdbl  = dir ? xdbl_b  : xdbl_f;
    const float* __restrict__ xz    = dir ? xz_b    : xz_f;
    const float* __restrict__ Alog  = dir ? Alog_b  : Alog_f;
    const float* __restrict__ Dp    = dir ? D_b     : D_f;
    float* ygp                      = dir ? ygp_b   : ygp_f;

    int ch = blockIdx.x * 128 + threadIdx.x;
    int b  = blockIdx.y;

    float Aev[32];
    #pragma unroll
    for (int n=0;n<32;n++) Aev[n] = -__expf(__ldg(&Alog[ch*32 + n]));
    float Dch = __ldg(&Dp[ch]);
    float h[32];
    #pragma unroll
    for (int n=0;n<32;n++) h[n] = 0.f;

    /* permuted-write constants for this channel (K=DI, nK8=128) */
    int kc = ch>>3;
    int tg = ch&3;
    int chb = ((ch>>2)&1)<<1;

    int t0 = dir ? (LSEQ-1) : 0;
    size_t row0 = (size_t)b*LSEQ + t0;
    float d  = __ldg(&delta[row0*DI + ch]);
    float u  = __ldg(&xc[row0*DI + ch]);
    float zz = __ldg(&xz[row0*(2*DI) + DI + ch]);

    for (int s=0;s<LSEQ;s++){
        int t = dir ? (LSEQ-1 - s) : s;
        float dn=0.f, un=0.f, zn=0.f;
        if (s+1 < LSEQ){
            int tn = dir ? (t-1) : (t+1);
            size_t rn = (size_t)b*LSEQ + tn;
            dn = __ldg(&delta[rn*DI + ch]);
            un = __ldg(&xc[rn*DI + ch]);
            zn = __ldg(&xz[rn*(2*DI) + DI + ch]);
        }
        size_t row = (size_t)b*LSEQ + t;
        const float4* Bp = (const float4*)(xdbl + row*96 + 32);
        const float4* Cp = (const float4*)(xdbl + row*96 + 64);
        float du = d * u;
        float y = 0.f;
        #pragma unroll
        for (int q=0;q<8;q++){
            float4 B4 = __ldg(&Bp[q]);
            float4 C4 = __ldg(&Cp[q]);
            int n = q*4;
            float dA;
            dA = __expf(d*Aev[n+0]); h[n+0] = fmaf(dA, h[n+0], du*B4.x); y = fmaf(h[n+0], C4.x, y);
            dA = __expf(d*Aev[n+1]); h[n+1] = fmaf(dA, h[n+1], du*B4.y); y = fmaf(h[n+1], C4.y, y);
            dA = __expf(d*Aev[n+2]); h[n+2] = fmaf(dA, h[n+2], du*B4.z); y = fmaf(h[n+2], C4.z, y);
            dA = __expf(d*Aev[n+3]); h[n+3] = fmaf(dA, h[n+3], du*B4.w); y = fmaf(h[n+3], C4.w, y);
        }
        float yv = fmaf(u, Dch, y);
        float sz = zz / (1.0f + __expf(-zz));
        /* permuted store: m = b*LSEQ+t ; mr = t&127 ; mt = b*8 + (t>>7) */
        int mr = t & 127;
        int mt = (b<<3) + (t>>7);
        size_t poff = ((size_t)(mt*128 + kc)*8 + (mr>>4))*128
                    + (size_t)((((mr&7)<<2) + tg)<<2) + ((mr>>3)&1) + chb;
        ygp[poff] = rnd_tf32(yv * sz);
        d = dn; u = un; zz = zn;
    }
}

/* ---------------- layernorm helpers ---------------- */
__device__ __forceinline__ float block_sum128(float v, float* sh){
    #pragma unroll
    for (int o=16;o>0;o>>=1) v += __shfl_xor_sync(0xffffffffu, v, o);
    if ((threadIdx.x & 31) == 0) sh[threadIdx.x >> 5] = v;
    __syncthreads();
    float r = sh[0] + sh[1] + sh[2] + sh[3];
    __syncthreads();
    return r;
}

/* out1 = LN(hf*pw0 + hb*pw1 + pb + x): writes row-major (residual) + permuted (FFN A) */
__global__ __launch_bounds__(128) void combine_ln(
    const float* __restrict__ of, const float* __restrict__ ob, const float* __restrict__ x,
    const float* __restrict__ pw, const float* __restrict__ pb,
    const float* __restrict__ g, const float* __restrict__ be,
    float* __restrict__ out, float* __restrict__ outp)
{
    __shared__ float sh[4];
    size_t m = blockIdx.x;
    float w0 = __ldg(&pw[0]), w1 = __ldg(&pw[1]), b0 = __ldg(&pb[0]);
    float v[4]; float s = 0.f;
    #pragma unroll
    for (int i=0;i<4;i++){
        int n = threadIdx.x + i*128;
        size_t idx = m*DM + n;
        float val = fmaf(of[idx], w0, fmaf(ob[idx], w1, b0 + x[idx]));
        v[i] = val; s += val;
    }
    float mu = block_sum128(s, sh) * (1.f/(float)DM);
    float s2 = 0.f;
    #pragma unroll
    for (int i=0;i<4;i++){ float dd = v[i]-mu; s2 = fmaf(dd,dd,s2); }
    float inv = rsqrtf(block_sum128(s2, sh)*(1.f/(float)DM) + 1e-12f);
    #pragma unroll
    for (int i=0;i<4;i++){
        int n = threadIdx.x + i*128;
        float val = rnd_tf32(fmaf((v[i]-mu)*inv, g[n], be[n]));
        out[m*DM + n] = val;
        outp[perm_off((int)m, n, DM/8)] = val;
    }
}

__global__ __launch_bounds__(128) void add_ln(
    const float* __restrict__ a, const float* __restrict__ r,
    const float* __restrict__ g, const float* __restrict__ be, float* __restrict__ out)
{
    __shared__ float sh[4];
    size_t m = blockIdx.x;
    float v[4]; float s = 0.f;
    #pragma unroll
    for (int i=0;i<4;i++){
        int n = threadIdx.x + i*128;
        size_t idx = m*DM + n;
        float val = a[idx] + r[idx];
        v[i] = val; s += val;
    }
    float mu = block_sum128(s, sh) * (1.f/(float)DM);
    float s2 = 0.f;
    #pragma unroll
    for (int i=0;i<4;i++){ float dd = v[i]-mu; s2 = fmaf(dd,dd,s2); }
    float inv = rsqrtf(block_sum128(s2, sh)*(1.f/(float)DM) + 1e-12f);
    #pragma unroll
    for (int i=0;i<4;i++){
        int n = threadIdx.x + i*128;
        out[m*DM + n] = fmaf((v[i]-mu)*inv, g[n], be[n]);
    }
}

/* ---------------- eager init ---------------- */
namespace {
struct EagerInit {
    float* base;
    EagerInit() : base(nullptr) {
        void* p = nullptr;
        cudaGetSymbolAddress(&p, g_arena);
        base = (float*)p;
        cudaFuncSetAttribute(mm_perm<0,0,0>, cudaFuncAttributeMaxDynamicSharedMemorySize, MM_SMEM);
        cudaFuncSetAttribute(mm_perm<0,1,0>, cudaFuncAttributeMaxDynamicSharedMemorySize, MM_SMEM);
        cudaFuncSetAttribute(mm_perm<3,0,0>, cudaFuncAttributeMaxDynamicSharedMemorySize, MM_SMEM);
        cudaFuncSetAttribute(mm_perm<2,1,1>, cudaFuncAttributeMaxDynamicSharedMemorySize, MM_SMEM);
        cudaFuncSetAttribute(mm_perm<1,0,0>, cudaFuncAttributeMaxDynamicSharedMemorySize, MM_SMEM);
    }
};
EagerInit g_eager;
}

/* ---------------- host helpers ---------------- */
static inline void runPermB(const float* s, float* d, int N, int K){
    int total = ((N+127)/128) * (K/8) * 1024;
    permB<<<(total+255)/256, 256>>>(s, d, N, K, total);
}
static inline void runPermA(const float* s, float* d, int lda, int K){
    int total = (MROWS/128) * (K/8) * 1024;
    permA<<<(total+255)/256, 256>>>(s, d, lda, K, total);
}

extern "C" void kernel_launch(void* const* d_in, const int* in_sizes, int n_in,
                              void* d_out, int out_size)
{
    const float* X        = (const float*)d_in[0];
    /* d_in[1] = lengths (unused by the reference) */
    const float* f_in_w   = (const float*)d_in[2];
    const float* f_conv_w = (const float*)d_in[3];
    const float* f_conv_b = (const float*)d_in[4];
    const float* f_xproj  = (const float*)d_in[5];
    const float* f_dt_w   = (const float*)d_in[6];
    const float* f_dt_b   = (const float*)d_in[7];
    const float* f_A_log  = (const float*)d_in[8];
    const float* f_D      = (const float*)d_in[9];
    const float* f_out_w  = (const float*)d_in[10];
    const float* b_in_w   = (const float*)d_in[11];
    const float* b_conv_w = (const float*)d_in[12];
    const float* b_conv_b = (const float*)d_in[13];
    const float* b_xproj  = (const float*)d_in[14];
    const float* b_dt_w   = (const float*)d_in[15];
    const float* b_dt_b   = (const float*)d_in[16];
    const float* b_A_log  = (const float*)d_in[17];
    const float* b_D      = (const float*)d_in[18];
    const float* b_out_w  = (const float*)d_in[19];
    const float* proj_w   = (const float*)d_in[20];
    const float* proj_b   = (const float*)d_in[21];
    const float* ln_g     = (const float*)d_in[22];
    const float* ln_b     = (const float*)d_in[23];
    const float* ffn_w1   = (const float*)d_in[24];
    const float* ffn_b1   = (const float*)d_in[25];
    const float* ffn_w2   = (const float*)d_in[26];
    const float* ffn_b2   = (const float*)d_in[27];
    const float* ffn_ln_g = (const float*)d_in[28];
    const float* ffn_ln_b = (const float*)d_in[29];

    float* base = g_eager.base;
    if (!base){ void* p = nullptr; cudaGetSymbolAddress(&p, g_arena); base = (float*)p; }

    float* xz_f   = base + OFF_XZ_F;
    float* xz_b   = base + OFF_XZ_B;
    float* xc_f   = base + OFF_XC_F;
    float* xc_b   = base + OFF_XC_B;
    float* dlt_f  = base + OFF_DLT_F;
    float* dlt_b  = base + OFF_DLT_B;
    float* xdbl_f = base + OFF_XDBL_F;
    float* xdbl_b = base + OFF_XDBL_B;
    float* out_f  = base + OFF_OUT_F;
    float* out_b  = base + OFF_OUT_B;
    float* out1   = base + OFF_OUT1;
    float* ffno   = base + OFF_FFNO;
    float* Xp     = base + OFF_XP;
    float* xcp_f  = base + OFF_XCP_F;
    float* xcp_b  = base + OFF_XCP_B;
    float* ygp_f  = base + OFF_YGP_F;
    float* ygp_b  = base + OFF_YGP_B;
    float* out1p  = base + OFF_OUT1P;
    float* ffnhp  = base + OFF_FFNHP;
    float* dtap_f = base + OFF_DTAP_F;
    float* dtap_b = base + OFF_DTAP_B;
    float* fiwP   = base + OFF_FIWP;
    float* biwP   = base + OFF_BIWP;
    float* fxpP   = base + OFF_FXPP;
    float* bxpP   = base + OFF_BXPP;
    float* fdtP   = base + OFF_FDTP;
    float* bdtP   = base + OFF_BDTP;
    float* fowP   = base + OFF_FOWP;
    float* bowP   = base + OFF_BOWP;
    float* w1P    = base + OFF_W1P;
    float* w2P    = base + OFF_W2P;
    float* OUT    = (float*)d_out;

    /* 0) permute weights + X into fragment-ordered tf32 layouts */
    runPermB(f_in_w, fiwP, 2*DI, DM);   runPermB(b_in_w, biwP, 2*DI, DM);
    runPermB(f_xproj, fxpP, 96, DI);    runPermB(b_xproj, bxpP, 96, DI);
    runPermB(f_dt_w, fdtP, DI, 32);     runPermB(b_dt_w, bdtP, DI, 32);
    runPermB(f_out_w, fowP, DM, DI);    runPermB(b_out_w, bowP, DM, DI);
    runPermB(ffn_w1, w1P, 4*DM, DM);    runPermB(ffn_w2, w2P, DM, 4*DM);
    runPermA(X, Xp, DM, DM);

    /* 1) in_proj both dirs: xz = X @ in_w^T  (N=2048, K=512) */
    mm_perm<0,0,0><<<dim3(16,64,2),128,MM_SMEM>>>(Xp, Xp, fiwP, biwP,
                                                  nullptr, nullptr, xz_f, xz_b, 2*DI,
                                                  2*DI, DM, 0);

    /* 2) depthwise conv + silu: xc row-major + permuted */
    conv_silu<<<dim3((LSEQ*DI)/256, BSZ, 2),256>>>(xz_f, xz_b,
                                                   f_conv_w, f_conv_b, b_conv_w, b_conv_b,
                                                   xc_f, xc_b, xcp_f, xcp_b);

    /* 3) x_dbl = xc @ xproj^T  (N=96 padded 128, K=1024), rounded out */
    mm_perm<0,1,0><<<dim3(1,64,2),128,MM_SMEM>>>(xcp_f, xcp_b, fxpP, bxpP,
                                                 nullptr, nullptr, xdbl_f, xdbl_b, 96,
                                                 96, DI, 0);

    /* 3b) dt-part of xdbl -> permuted A for GEMM4 (overlays dead Xp) */
    runPermA(xdbl_f, dtap_f, 96, 32);
    runPermA(xdbl_b, dtap_b, 96, 32);

    /* 4) delta = softplus(dt @ dt_w^T + dt_b)  (N=1024, K=32) */
    mm_perm<3,0,0><<<dim3(8,64,2),128,MM_SMEM>>>(dtap_f, dtap_b, fdtP, bdtP,
                                                 f_dt_b, b_dt_b, dlt_f, dlt_b, DI,
                                                 DI, 32, 0);

    /* 5) selective scan + u*D + silu(z) gate -> ygp (overlays dead xcp) */
    scan_gate<<<dim3(DI/128, BSZ, 2),128>>>(dlt_f, dlt_b, xc_f, xc_b,
                                            xdbl_f, xdbl_b, xz_f, xz_b,
                                            f_A_log, b_A_log, f_D, b_D,
                                            ygp_f, ygp_b);

    /* 6) out_proj: yg @ out_w^T  (N=512, K=1024); out_f/out_b overlay dead xz head */
    mm_perm<0,0,0><<<dim3(4,64,2),128,MM_SMEM>>>(ygp_f, ygp_b, fowP, bowP,
                                                 nullptr, nullptr, out_f, out_b, DM,
                                                 DM, DI, 0);

    /* 7) out1 = LN(hf*pw0 + hb*pw1 + pb + x): row-major + permuted */
    combine_ln<<<MROWS,128>>>(out_f, out_b, X, proj_w, proj_b, ln_g, ln_b,
                              out1, out1p);

    /* 8) FFN up + gelu -> ffnhp permuted (Kout=2048)  (N=2048, K=512) */
    mm_perm<2,1,1><<<dim3(16,64,1),128,MM_SMEM>>>(out1p, out1p, w1P, w1P,
                                                  ffn_b1, ffn_b1, ffnhp, ffnhp, 0,
                                                  4*DM, DM, (4*DM)/8);

    /* 9) FFN down + bias  (N=512, K=2048) */
    mm_perm<1,0,0><<<dim3(4,64,1),128,MM_SMEM>>>(ffnhp, ffnhp, w2P, w2P,
                                                 ffn_b2, ffn_b2, ffno, ffno, DM,
                                                 DM, 4*DM, 0);

    /* 10) final = LN(ffn_out + out1) */
    add_ln<<<MROWS,128>>>(ffno, out1, ffn_ln_g, ffn_ln_b, OUT);
}

// round 15
// speedup vs baseline: 1.4827x; 1.1681x over previous
#include <cuda_runtime.h>
#include <math.h>
#include <stdint.h>

#define BSZ   8
#define LSEQ  1024
#define DM    512
#define DI    1024
#define MROWS (BSZ*LSEQ)   /* 8192 */

/* ---------------- arena: offsets in units of 1M floats (total 96MF = 384MB) ------ */
#define MF 1048576ull
#define OFF_XZ_F   (0*MF)
#define OFF_XZ_B   (16*MF)
#define OFF_XC_F   (32*MF)
#define OFF_XC_B   (40*MF)
#define OFF_DLT_F  (48*MF)
#define OFF_DLT_B  (56*MF)
#define OFF_XDBL_F (64*MF)
#define OFF_XDBL_B (65*MF)
#define OFF_XCP_F  (66*MF)
#define OFF_XCP_B  (74*MF)
#define OFF_XP     (82*MF)
#define OFF_FIWP   (86*MF)
#define OFF_BIWP   (87*MF)
#define OFF_FXPP   (88*MF)
#define OFF_BXPP   (89*MF)
#define OFF_FDTP   (90*MF)
#define OFF_BDTP   (91*MF)
#define OFF_FOWP   (92*MF)
#define OFF_BOWP   (93*MF)
#define OFF_W1P    (94*MF)
#define OFF_W2P    (95*MF)
#define ARENA_FLOATS (96*MF)
/* overlays (lifetimes disjoint):
   ygp_f/b  -> xcp_f/b  (xcp dead after GEMM3; scan reads row-major xc)
   dtap_f/b -> Xp       (Xp dead after GEMM1)
   out_f=0, out_b=4, out1=8, out1p=12, ffnhp=16, ffno=32   (xz/xc dead after scan) */
#define OFF_YGP_F  OFF_XCP_F
#define OFF_YGP_B  OFF_XCP_B
#define OFF_DTAP_F (82*MF)
#define OFF_DTAP_B (83*MF)
#define OFF_OUT_F  (0*MF)
#define OFF_OUT_B  (4*MF)
#define OFF_OUT1   (8*MF)
#define OFF_OUT1P  (12*MF)
#define OFF_FFNHP  (16*MF)
#define OFF_FFNO   (32*MF)

__device__ float g_arena[ARENA_FLOATS];

__device__ __forceinline__ uint32_t f2tf32(float x){
    uint32_t r; asm("cvt.rna.tf32.f32 %0, %1;" : "=r"(r) : "f"(x)); return r;
}
__device__ __forceinline__ float rnd_tf32(float x){ return __uint_as_float(f2tf32(x)); }

__device__ __forceinline__ uint32_t smem_u32(const void* p){
    uint32_t a;
    asm("{ .reg .u64 t; cvta.to.shared.u64 t, %1; cvt.u32.u64 %0, t; }" : "=r"(a) : "l"(p));
    return a;
}
__device__ __forceinline__ void cp16(uint32_t dst, const float* src){
    asm volatile("cp.async.cg.shared.global [%0], [%1], 16;"
                 :: "r"(dst), "l"(src) : "memory");
}
__device__ __forceinline__ void mma_tf32(float* d, const uint32_t* a, const uint32_t* b){
    asm volatile("mma.sync.aligned.m16n8k8.row.col.f32.tf32.tf32.f32 "
                 "{%0,%1,%2,%3}, {%4,%5,%6,%7}, {%8,%9}, {%0,%1,%2,%3};"
                 : "+f"(d[0]), "+f"(d[1]), "+f"(d[2]), "+f"(d[3])
                 : "r"(a[0]), "r"(a[1]), "r"(a[2]), "r"(a[3]),
                   "r"(b[0]), "r"(b[1]));
}

/* permuted A-layout offset for element (m,k); nK8 = K/8.
   word order per lane: w0=(g,tig) w1=(g+8,tig) w2=(g,tig+4) w3=(g+8,tig+4) */
__device__ __forceinline__ size_t perm_off(int m, int k, int nK8){
    int mt = m>>7, mr = m&127;
    int fb = mr>>4, r16 = mr&15;
    int kc = k>>3, kr = k&7;
    return ((size_t)(mt*nK8 + kc)*8 + fb)*128
         + (size_t)((((r16&7)<<2) + (kr&3))<<2) + (r16>>3) + ((kr>>2)<<1);
}

/* ---------------- epilogues ---------------- */
template<int EPI, int RND>
__device__ __forceinline__ float epi_apply(float v, const float* __restrict__ bias, int n){
    float x = v;
    if (EPI != 0){
        x = v + bias[n];
        if (EPI == 2) x = 0.5f * x * (1.0f + erff(x * 0.70710678118654752f)); /* exact gelu */
        else if (EPI == 3) x = (x > 20.0f) ? x : log1pf(__expf(x));           /* softplus */
    }
    return RND ? rnd_tf32(x) : x;
}

/* ---------------- permute kernels (inputs -> fragment-ordered tf32) ---------------- */
/* B layout: ((ntile*nK8+kc)*16 + jb)*64 + (g*4+tig)*2 + w ; element: n=ntile*128+jb*8+g,
   k=kc*8+w*4+tig.  Index bit fields: w=bit0, lane=bits1-5, jb=bits6-9, blk=bits10+. */
__global__ __launch_bounds__(256) void permB(const float* __restrict__ src,
                                             float* __restrict__ dst,
                                             int N, int K, int total){
    int idx = blockIdx.x*256 + threadIdx.x;
    if (idx >= total) return;
    int w = idx & 1, lane = (idx>>1)&31, jb = (idx>>6)&15;
    int blk = idx>>10;
    int nK8 = K>>3;
    int kc = blk % nK8, ntile = blk / nK8;
    int n = ntile*128 + jb*8 + (lane>>2);
    int k = kc*8 + w*4 + (lane&3);
    dst[idx] = (n < N) ? rnd_tf32(src[(size_t)n*K + k]) : 0.f;
}
/* A layout: ((mt*nK8+kc)*8 + fb)*128 + (g*4+tig)*4 + w
   bit fields: w=bits0-1, lane=bits2-6, fb=bits7-9, blk=bits10+ */
__global__ __launch_bounds__(256) void permA(const float* __restrict__ src,
                                             float* __restrict__ dst,
                                             int lda, int K, int total){
    int idx = blockIdx.x*256 + threadIdx.x;
    if (idx >= total) return;
    int w = idx & 3, lane = (idx>>2)&31, fb = (idx>>7)&7;
    int blk = idx>>10;
    int nK8 = K>>3;
    int kc = blk % nK8, mt = blk / nK8;
    int m = mt*128 + fb*16 + (w&1)*8 + (lane>>2);
    int k = kc*8 + (w>>1)*4 + (lane&3);
    dst[idx] = rnd_tf32(src[(size_t)m*lda + k]);
}

/* ---------------- TF32 HMMA GEMM v3 on pre-permuted operands ----------------
   C[m,n] = sum_k A[m,k]*W[n,k].  CTA 128x128, 4 warps (warp tile 64x64, 4x8 frags).
   K-chunks of 32: cp.async identity copy of 16KB A + 16KB B, 2-stage.
   OUTP=1: store C permuted (A-layout for the NEXT gemm, Kdim nK8o). */
#define MM_SMEM 65536

template<int EPI, int RND, int OUTP>
__global__ __launch_bounds__(128) void mm_perm(
    const float* __restrict__ A0, const float* __restrict__ A1,
    const float* __restrict__ B0, const float* __restrict__ B1,
    const float* __restrict__ bias0, const float* __restrict__ bias1,
    float* __restrict__ C0, float* __restrict__ C1, int ldc,
    int N, int K, int nK8o)
{
    extern __shared__ float smem[];   /* [A: 2x4096][B: 2x4096] floats */
    const float* A    = blockIdx.z ? A1 : A0;
    const float* B    = blockIdx.z ? B1 : B0;
    const float* bias = blockIdx.z ? bias1 : bias0;
    float*       C    = blockIdx.z ? C1 : C0;

    int tid = threadIdx.x, wid = tid>>5, lane = tid&31;
    int wm = wid & 1, wn = wid >> 1;
    int g = lane>>2, tig = lane&3;
    int nK8 = K>>3;
    int KC  = K>>5;

    const float* Ach = A + ((size_t)blockIdx.y * nK8) * 1024;
    const float* Bch = B + ((size_t)blockIdx.x * nK8) * 1024;

    uint32_t sbase = smem_u32(smem);
    uint32_t sa_d = sbase + tid*128;            /* + stage*16384 */
    uint32_t sb_d = sbase + 32768 + tid*128;

    float acc[4][8][4];
    #pragma unroll
    for (int f=0;f<4;f++)
        #pragma unroll
        for (int j=0;j<8;j++)
            #pragma unroll
            for (int q=0;q<4;q++) acc[f][j][q] = 0.f;

    /* prologue: chunk 0 -> stage 0 (identity copy, 128B per thread per operand) */
    #pragma unroll
    for (int q=0;q<8;q++){
        cp16(sa_d + q*16, Ach + tid*32 + q*4);
        cp16(sb_d + q*16, Bch + tid*32 + q*4);
    }
    asm volatile("cp.async.commit_group;" ::: "memory");

    for (int c=0;c<KC;c++){
        asm volatile("cp.async.wait_group 0;" ::: "memory");
        __syncthreads();
        if (c+1 < KC){
            int st = (c+1)&1;
            const float* ag = Ach + (size_t)(c+1)*4096;
            const float* bg = Bch + (size_t)(c+1)*4096;
            uint32_t da = sa_d + st*16384;
            uint32_t db = sb_d + st*16384;
            #pragma unroll
            for (int q=0;q<8;q++){
                cp16(da + q*16, ag + tid*32 + q*4);
                cp16(db + q*16, bg + tid*32 + q*4);
            }
        }
        asm volatile("cp.async.commit_group;" ::: "memory");

        const float* sAs = smem + (c&1)*4096;
        const float* sBs = smem + 8192 + (c&1)*4096;
        #pragma unroll
        for (int s=0;s<4;s++){
            uint32_t af[4][4], bf[8][2];
            #pragma unroll
            for (int f=0;f<4;f++)
                *(uint4*)af[f] = *(const uint4*)&sAs[s*1024 + (wm*4+f)*128 + lane*4];
            #pragma unroll
            for (int j=0;j<8;j++)
                *(uint2*)bf[j] = *(const uint2*)&sBs[s*1024 + (wn*8+j)*64 + lane*2];
            #pragma unroll
            for (int f=0;f<4;f++)
                #pragma unroll
                for (int j=0;j<8;j++)
                    mma_tf32(acc[f][j], af[f], bf[j]);
        }
    }

    /* epilogue */
    #pragma unroll
    for (int f=0;f<4;f++){
        int row = blockIdx.y*128 + wm*64 + f*16 + g;
        #pragma unroll
        for (int j=0;j<8;j++){
            int nb = blockIdx.x*128 + wn*64 + j*8;
            int cn = nb + tig*2;
            if (!OUTP){
                if (nb < N){
                    float2 v;
                    v.x = epi_apply<EPI,RND>(acc[f][j][0], bias, cn);
                    v.y = epi_apply<EPI,RND>(acc[f][j][1], bias, cn+1);
                    *(float2*)&C[(size_t)row * ldc + cn] = v;
                    v.x = epi_apply<EPI,RND>(acc[f][j][2], bias, cn);
                    v.y = epi_apply<EPI,RND>(acc[f][j][3], bias, cn+1);
                    *(float2*)&C[(size_t)(row+8) * ldc + cn] = v;
                }
            } else {
                #pragma unroll
                for (int q=0;q<4;q++){
                    int m = row + (q>>1)*8;
                    int k = cn + (q&1);
                    C[perm_off(m, k, nK8o)] = epi_apply<EPI,RND>(acc[f][j][q], bias, k);
                }
            }
        }
    }
}

/* ---------------- conv + SiLU: writes xc (row-major, scan) AND xcp (permuted) ---- */
__global__ __launch_bounds__(256) void conv_silu(
    const float* __restrict__ xzf, const float* __restrict__ xzb,
    const float* __restrict__ fw, const float* __restrict__ fbias,
    const float* __restrict__ bw, const float* __restrict__ bbias,
    float* __restrict__ xcf, float* __restrict__ xcb,
    float* __restrict__ xcpf, float* __restrict__ xcpb)
{
    int lin = blockIdx.x * 256 + threadIdx.x;
    int ch = lin & (DI-1);
    int t  = lin >> 10;
    int b  = blockIdx.y;
    int dir = blockIdx.z;
    const float* __restrict__ xin = dir ? xzb : xzf;
    const float* __restrict__ cw  = dir ? bw : fw;
    const float* __restrict__ cb  = dir ? bbias : fbias;
    float* out  = dir ? xcb : xcf;
    float* outp = dir ? xcpb : xcpf;

    float acc = __ldg(&cb[ch]);
    float w0 = __ldg(&cw[ch*4+0]), w1 = __ldg(&cw[ch*4+1]);
    float w2 = __ldg(&cw[ch*4+2]), w3 = __ldg(&cw[ch*4+3]);
    size_t base = ((size_t)b * LSEQ) * (2*DI) + ch;
    if (dir == 0){
        if (t-3 >= 0) acc = fmaf(w0, __ldg(&xin[base + (size_t)(t-3)*(2*DI)]), acc);
        if (t-2 >= 0) acc = fmaf(w1, __ldg(&xin[base + (size_t)(t-2)*(2*DI)]), acc);
        if (t-1 >= 0) acc = fmaf(w2, __ldg(&xin[base + (size_t)(t-1)*(2*DI)]), acc);
        acc = fmaf(w3, __ldg(&xin[base + (size_t)t*(2*DI)]), acc);
    } else {
        if (t+3 < LSEQ) acc = fmaf(w0, __ldg(&xin[base + (size_t)(t+3)*(2*DI)]), acc);
        if (t+2 < LSEQ) acc = fmaf(w1, __ldg(&xin[base + (size_t)(t+2)*(2*DI)]), acc);
        if (t+1 < LSEQ) acc = fmaf(w2, __ldg(&xin[base + (size_t)(t+1)*(2*DI)]), acc);
        acc = fmaf(w3, __ldg(&xin[base + (size_t)t*(2*DI)]), acc);
    }
    float v = rnd_tf32(acc / (1.0f + __expf(-acc)));
    int m = b*LSEQ + t;
    out[(size_t)m*DI + ch] = v;
    outp[perm_off(m, ch, DI/8)] = v;
}

/* ---------------- selective scan + gating: writes ygp (permuted only) ---------- */
__global__ __launch_bounds__(128) void scan_gate(
    const float* __restrict__ delta_f, const float* __restrict__ delta_b,
    const float* __restrict__ xc_f,    const float* __restrict__ xc_b,
    const float* __restrict__ xdbl_f,  const float* __restrict__ xdbl_b,
    const float* __restrict__ xz_f,    const float* __restrict__ xz_b,
    const float* __restrict__ Alog_f,  const float* __restrict__ Alog_b,
    const float* __restrict__ D_f,     const float* __restrict__ D_b,
    float* __restrict__ ygp_f, float* __restrict__ ygp_b)
{
    int dir = blockIdx.z;
    const float* __restrict__ delta = dir ? delta_b : delta_f;
    const float* __restrict__ xc    = dir ? xc_b    : xc_f;
    const float* __restrict__ xdbl  = dir ? xdbl_b  : xdbl_f;
    const float* __restrict__ xz    = dir ? xz_b    : xz_f;
    const float* __restrict__ Alog  = dir ? Alog_b  : Alog_f;
    const float* __restrict__ Dp    = dir ? D_b     : D_f;
    float* ygp                      = dir ? ygp_b   : ygp_f;

    int ch = blockIdx.x * 128 + threadIdx.x;
    int b  = blockIdx.y;

    float Aev[32];
    #pragma unroll
    for (int n=0;n<32;n++) Aev[n] = -__expf(__ldg(&Alog[ch*32 + n]));
    float Dch = __ldg(&Dp[ch]);
    float h[32];
    #pragma unroll
    for (int n=0;n<32;n++) h[n] = 0.f;

    /* permuted-write constants for this channel (K=DI, nK8=128) */
    int kc = ch>>3;
    int tg = ch&3;
    int chb = ((ch>>2)&1)<<1;

    int t0 = dir ? (LSEQ-1) : 0;
    size_t row0 = (size_t)b*LSEQ + t0;
    float d  = __ldg(&delta[row0*DI + ch]);
    float u  = __ldg(&xc[row0*DI + ch]);
    float zz = __ldg(&xz[row0*(2*DI) + DI + ch]);

    for (int s=0;s<LSEQ;s++){
        int t = dir ? (LSEQ-1 - s) : s;
        /* L1 prefetch of the B/C row two timesteps ahead (row spans 256B) */
        if (s+2 < LSEQ){
            int tp = dir ? (t-2) : (t+2);
            const float* pf = xdbl + ((size_t)b*LSEQ + tp)*96 + 32;
            asm volatile("prefetch.global.L1 [%0];" :: "l"(pf));
            asm volatile("prefetch.global.L1 [%0];" :: "l"(pf+32));
            asm volatile("prefetch.global.L1 [%0];" :: "l"(pf+63));
        }
        float dn=0.f, un=0.f, zn=0.f;
        if (s+1 < LSEQ){
            int tn = dir ? (t-1) : (t+1);
            size_t rn = (size_t)b*LSEQ + tn;
            dn = __ldg(&delta[rn*DI + ch]);
            un = __ldg(&xc[rn*DI + ch]);
            zn = __ldg(&xz[rn*(2*DI) + DI + ch]);
        }
        size_t row = (size_t)b*LSEQ + t;
        const float4* Bp = (const float4*)(xdbl + row*96 + 32);
        const float4* Cp = (const float4*)(xdbl + row*96 + 64);
        float du = d * u;
        float y = 0.f;
        #pragma unroll
        for (int q=0;q<8;q++){
            float4 B4 = __ldg(&Bp[q]);
            float4 C4 = __ldg(&Cp[q]);
            int n = q*4;
            float dA;
            dA = __expf(d*Aev[n+0]); h[n+0] = fmaf(dA, h[n+0], du*B4.x); y = fmaf(h[n+0], C4.x, y);
            dA = __expf(d*Aev[n+1]); h[n+1] = fmaf(dA, h[n+1], du*B4.y); y = fmaf(h[n+1], C4.y, y);
            dA = __expf(d*Aev[n+2]); h[n+2] = fmaf(dA, h[n+2], du*B4.z); y = fmaf(h[n+2], C4.z, y);
            dA = __expf(d*Aev[n+3]); h[n+3] = fmaf(dA, h[n+3], du*B4.w); y = fmaf(h[n+3], C4.w, y);
        }
        float yv = fmaf(u, Dch, y);
        float sz = zz / (1.0f + __expf(-zz));
        /* permuted store: m = b*LSEQ+t ; mr = t&127 ; mt = b*8 + (t>>7) */
        int mr = t & 127;
        int mt = (b<<3) + (t>>7);
        size_t poff = ((size_t)(mt*128 + kc)*8 + (mr>>4))*128
                    + (size_t)((((mr&7)<<2) + tg)<<2) + ((mr>>3)&1) + chb;
        ygp[poff] = rnd_tf32(yv * sz);
        d = dn; u = un; zz = zn;
    }
}

/* ---------------- layernorm helpers ---------------- */
__device__ __forceinline__ float block_sum128(float v, float* sh){
    #pragma unroll
    for (int o=16;o>0;o>>=1) v += __shfl_xor_sync(0xffffffffu, v, o);
    if ((threadIdx.x & 31) == 0) sh[threadIdx.x >> 5] = v;
    __syncthreads();
    float r = sh[0] + sh[1] + sh[2] + sh[3];
    __syncthreads();
    return r;
}

/* out1 = LN(hf*pw0 + hb*pw1 + pb + x): writes row-major (residual) + permuted (FFN A) */
__global__ __launch_bounds__(128) void combine_ln(
    const float* __restrict__ of, const float* __restrict__ ob, const float* __restrict__ x,
    const float* __restrict__ pw, const float* __restrict__ pb,
    const float* __restrict__ g, const float* __restrict__ be,
    float* __restrict__ out, float* __restrict__ outp)
{
    __shared__ float sh[4];
    size_t m = blockIdx.x;
    float w0 = __ldg(&pw[0]), w1 = __ldg(&pw[1]), b0 = __ldg(&pb[0]);
    float v[4]; float s = 0.f;
    #pragma unroll
    for (int i=0;i<4;i++){
        int n = threadIdx.x + i*128;
        size_t idx = m*DM + n;
        float val = fmaf(of[idx], w0, fmaf(ob[idx], w1, b0 + x[idx]));
        v[i] = val; s += val;
    }
    float mu = block_sum128(s, sh) * (1.f/(float)DM);
    float s2 = 0.f;
    #pragma unroll
    for (int i=0;i<4;i++){ float dd = v[i]-mu; s2 = fmaf(dd,dd,s2); }
    float inv = rsqrtf(block_sum128(s2, sh)*(1.f/(float)DM) + 1e-12f);
    #pragma unroll
    for (int i=0;i<4;i++){
        int n = threadIdx.x + i*128;
        float val = rnd_tf32(fmaf((v[i]-mu)*inv, g[n], be[n]));
        out[m*DM + n] = val;
        outp[perm_off((int)m, n, DM/8)] = val;
    }
}

__global__ __launch_bounds__(128) void add_ln(
    const float* __restrict__ a, const float* __restrict__ r,
    const float* __restrict__ g, const float* __restrict__ be, float* __restrict__ out)
{
    __shared__ float sh[4];
    size_t m = blockIdx.x;
    float v[4]; float s = 0.f;
    #pragma unroll
    for (int i=0;i<4;i++){
        int n = threadIdx.x + i*128;
        size_t idx = m*DM + n;
        float val = a[idx] + r[idx];
        v[i] = val; s += val;
    }
    float mu = block_sum128(s, sh) * (1.f/(float)DM);
    float s2 = 0.f;
    #pragma unroll
    for (int i=0;i<4;i++){ float dd = v[i]-mu; s2 = fmaf(dd,dd,s2); }
    float inv = rsqrtf(block_sum128(s2, sh)*(1.f/(float)DM) + 1e-12f);
    #pragma unroll
    for (int i=0;i<4;i++){
        int n = threadIdx.x + i*128;
        out[m*DM + n] = fmaf((v[i]-mu)*inv, g[n], be[n]);
    }
}

/* ---------------- eager init ---------------- */
namespace {
struct EagerInit {
    float* base;
    EagerInit() : base(nullptr) {
        void* p = nullptr;
        cudaGetSymbolAddress(&p, g_arena);
        base = (float*)p;
        cudaFuncSetAttribute(mm_perm<0,0,0>, cudaFuncAttributeMaxDynamicSharedMemorySize, MM_SMEM);
        cudaFuncSetAttribute(mm_perm<0,1,0>, cudaFuncAttributeMaxDynamicSharedMemorySize, MM_SMEM);
        cudaFuncSetAttribute(mm_perm<3,0,0>, cudaFuncAttributeMaxDynamicSharedMemorySize, MM_SMEM);
        cudaFuncSetAttribute(mm_perm<2,1,1>, cudaFuncAttributeMaxDynamicSharedMemorySize, MM_SMEM);
        cudaFuncSetAttribute(mm_perm<1,0,0>, cudaFuncAttributeMaxDynamicSharedMemorySize, MM_SMEM);
    }
};
EagerInit g_eager;
}

/* ---------------- host helpers ---------------- */
static inline void runPermB(const float* s, float* d, int N, int K){
    int total = ((N+127)/128) * (K/8) * 1024;
    permB<<<(total+255)/256, 256>>>(s, d, N, K, total);
}
static inline void runPermA(const float* s, float* d, int lda, int K){
    int total = (MROWS/128) * (K/8) * 1024;
    permA<<<(total+255)/256, 256>>>(s, d, lda, K, total);
}

extern "C" void kernel_launch(void* const* d_in, const int* in_sizes, int n_in,
                              void* d_out, int out_size)
{
    const float* X        = (const float*)d_in[0];
    /* d_in[1] = lengths (unused by the reference) */
    const float* f_in_w   = (const float*)d_in[2];
    const float* f_conv_w = (const float*)d_in[3];
    const float* f_conv_b = (const float*)d_in[4];
    const float* f_xproj  = (const float*)d_in[5];
    const float* f_dt_w   = (const float*)d_in[6];
    const float* f_dt_b   = (const float*)d_in[7];
    const float* f_A_log  = (const float*)d_in[8];
    const float* f_D      = (const float*)d_in[9];
    const float* f_out_w  = (const float*)d_in[10];
    const float* b_in_w   = (const float*)d_in[11];
    const float* b_conv_w = (const float*)d_in[12];
    const float* b_conv_b = (const float*)d_in[13];
    const float* b_xproj  = (const float*)d_in[14];
    const float* b_dt_w   = (const float*)d_in[15];
    const float* b_dt_b   = (const float*)d_in[16];
    const float* b_A_log  = (const float*)d_in[17];
    const float* b_D      = (const float*)d_in[18];
    const float* b_out_w  = (const float*)d_in[19];
    const float* proj_w   = (const float*)d_in[20];
    const float* proj_b   = (const float*)d_in[21];
    const float* ln_g     = (const float*)d_in[22];
    const float* ln_b     = (const float*)d_in[23];
    const float* ffn_w1   = (const float*)d_in[24];
    const float* ffn_b1   = (const float*)d_in[25];
    const float* ffn_w2   = (const float*)d_in[26];
    const float* ffn_b2   = (const float*)d_in[27];
    const float* ffn_ln_g = (const float*)d_in[28];
    const float* ffn_ln_b = (const float*)d_in[29];

    float* base = g_eager.base;
    if (!base){ void* p = nullptr; cudaGetSymbolAddress(&p, g_arena); base = (float*)p; }

    float* xz_f   = base + OFF_XZ_F;
    float* xz_b   = base + OFF_XZ_B;
    float* xc_f   = base + OFF_XC_F;
    float* xc_b   = base + OFF_XC_B;
    float* dlt_f  = base + OFF_DLT_F;
    float* dlt_b  = base + OFF_DLT_B;
    float* xdbl_f = base + OFF_XDBL_F;
    float* xdbl_b = base + OFF_XDBL_B;
    float* out_f  = base + OFF_OUT_F;
    float* out_b  = base + OFF_OUT_B;
    float* out1   = base + OFF_OUT1;
    float* ffno   = base + OFF_FFNO;
    float* Xp     = base + OFF_XP;
    float* xcp_f  = base + OFF_XCP_F;
    float* xcp_b  = base + OFF_XCP_B;
    float* ygp_f  = base + OFF_YGP_F;
    float* ygp_b  = base + OFF_YGP_B;
    float* out1p  = base + OFF_OUT1P;
    float* ffnhp  = base + OFF_FFNHP;
    float* dtap_f = base + OFF_DTAP_F;
    float* dtap_b = base + OFF_DTAP_B;
    float* fiwP   = base + OFF_FIWP;
    float* biwP   = base + OFF_BIWP;
    float* fxpP   = base + OFF_FXPP;
    float* bxpP   = base + OFF_BXPP;
    float* fdtP   = base + OFF_FDTP;
    float* bdtP   = base + OFF_BDTP;
    float* fowP   = base + OFF_FOWP;
    float* bowP   = base + OFF_BOWP;
    float* w1P    = base + OFF_W1P;
    float* w2P    = base + OFF_W2P;
    float* OUT    = (float*)d_out;

    /* 0a) GEMM1's inputs only (3 launches) so GEMM1 is launch index 3 -> ncu capture */
    runPermB(f_in_w, fiwP, 2*DI, DM);    /* idx 0 */
    runPermB(b_in_w, biwP, 2*DI, DM);    /* idx 1 */
    runPermA(X, Xp, DM, DM);             /* idx 2 */

    /* 1) in_proj both dirs: xz = X @ in_w^T  (N=2048, K=512)  -- launch index 3 */
    mm_perm<0,0,0><<<dim3(16,64,2),128,MM_SMEM>>>(Xp, Xp, fiwP, biwP,
                                                  nullptr, nullptr, xz_f, xz_b, 2*DI,
                                                  2*DI, DM, 0);

    /* 0b) remaining weight permutes (independent of GEMM1) */
    runPermB(f_xproj, fxpP, 96, DI);    runPermB(b_xproj, bxpP, 96, DI);
    runPermB(f_dt_w, fdtP, DI, 32);     runPermB(b_dt_w, bdtP, DI, 32);
    runPermB(f_out_w, fowP, DM, DI);    runPermB(b_out_w, bowP, DM, DI);
    runPermB(ffn_w1, w1P, 4*DM, DM);    runPermB(ffn_w2, w2P, DM, 4*DM);

    /* 2) depthwise conv + silu: xc row-major + permuted */
    conv_silu<<<dim3((LSEQ*DI)/256, BSZ, 2),256>>>(xz_f, xz_b,
                                                   f_conv_w, f_conv_b, b_conv_w, b_conv_b,
                                                   xc_f, xc_b, xcp_f, xcp_b);

    /* 3) x_dbl = xc @ xproj^T  (N=96 padded 128, K=1024), rounded out */
    mm_perm<0,1,0><<<dim3(1,64,2),128,MM_SMEM>>>(xcp_f, xcp_b, fxpP, bxpP,
                                                 nullptr, nullptr, xdbl_f, xdbl_b, 96,
                                                 96, DI, 0);

    /* 3b) dt-part of xdbl -> permuted A for GEMM4 (overlays dead Xp) */
    runPermA(xdbl_f, dtap_f, 96, 32);
    runPermA(xdbl_b, dtap_b, 96, 32);

    /* 4) delta = softplus(dt @ dt_w^T + dt_b)  (N=1024, K=32) */
    mm_perm<3,0,0><<<dim3(8,64,2),128,MM_SMEM>>>(dtap_f, dtap_b, fdtP, bdtP,
                                                 f_dt_b, b_dt_b, dlt_f, dlt_b, DI,
                                                 DI, 32, 0);

    /* 5) selective scan + u*D + silu(z) gate -> ygp (overlays dead xcp) */
    scan_gate<<<dim3(DI/128, BSZ, 2),128>>>(dlt_f, dlt_b, xc_f, xc_b,
                                            xdbl_f, xdbl_b, xz_f, xz_b,
                                            f_A_log, b_A_log, f_D, b_D,
                                            ygp_f, ygp_b);

    /* 6) out_proj: yg @ out_w^T  (N=512, K=1024); out_f/out_b overlay dead xz head */
    mm_perm<0,0,0><<<dim3(4,64,2),128,MM_SMEM>>>(ygp_f, ygp_b, fowP, bowP,
                                                 nullptr, nullptr, out_f, out_b, DM,
                                                 DM, DI, 0);

    /* 7) out1 = LN(hf*pw0 + hb*pw1 + pb + x): row-major + permuted */
    combine_ln<<<MROWS,128>>>(out_f, out_b, X, proj_w, proj_b, ln_g, ln_b,
                              out1, out1p);

    /* 8) FFN up + gelu -> ffnhp permuted (Kout=2048)  (N=2048, K=512) */
    mm_perm<2,1,1><<<dim3(16,64,1),128,MM_SMEM>>>(out1p, out1p, w1P, w1P,
                                                  ffn_b1, ffn_b1, ffnhp, ffnhp, 0,
                                                  4*DM, DM, (4*DM)/8);

    /* 9) FFN down + bias  (N=512, K=2048) */
    mm_perm<1,0,0><<<dim3(4,64,1),128,MM_SMEM>>>(ffnhp, ffnhp, w2P, w2P,
                                                 ffn_b2, ffn_b2, ffno, ffno, DM,
                                                 DM, 4*DM, 0);

    /* 10) final = LN(ffn_out + out1) */
    add_ln<<<MROWS,128>>>(ffno, out1, ffn_ln_g, ffn_ln_b, OUT);
}

// round 16
// speedup vs baseline: 1.4915x; 1.0059x over previous
#include <cuda_runtime.h>
#include <math.h>
#include <stdint.h>

#define BSZ   8
#define LSEQ  1024
#define DM    512
#define DI    1024
#define MROWS (BSZ*LSEQ)   /* 8192 */

/* ---------------- arena: offsets in units of 1M floats (total 96MF = 384MB) ------ */
#define MF 1048576ull
#define OFF_XZ_F   (0*MF)
#define OFF_XZ_B   (16*MF)
#define OFF_XC_F   (32*MF)
#define OFF_XC_B   (40*MF)
#define OFF_DLT_F  (48*MF)
#define OFF_DLT_B  (56*MF)
#define OFF_XDBL_F (64*MF)
#define OFF_XDBL_B (65*MF)
#define OFF_XCP_F  (66*MF)
#define OFF_XCP_B  (74*MF)
#define OFF_XP     (82*MF)
#define OFF_FIWP   (86*MF)
#define OFF_BIWP   (87*MF)
#define OFF_FXPP   (88*MF)
#define OFF_BXPP   (89*MF)
#define OFF_FDTP   (90*MF)
#define OFF_BDTP   (91*MF)
#define OFF_FOWP   (92*MF)
#define OFF_BOWP   (93*MF)
#define OFF_W1P    (94*MF)
#define OFF_W2P    (95*MF)
#define ARENA_FLOATS (96*MF)
/* overlays (lifetimes disjoint):
   ygp_f/b  -> xcp_f/b  (xcp dead after GEMM3; scan reads row-major xc)
   dtap_f/b -> Xp       (Xp dead after GEMM1)
   out_f=0, out_b=4, out1=8, out1p=12, ffnhp=16, ffno=32   (xz/xc dead after scan) */
#define OFF_YGP_F  OFF_XCP_F
#define OFF_YGP_B  OFF_XCP_B
#define OFF_DTAP_F (82*MF)
#define OFF_DTAP_B (83*MF)
#define OFF_OUT_F  (0*MF)
#define OFF_OUT_B  (4*MF)
#define OFF_OUT1   (8*MF)
#define OFF_OUT1P  (12*MF)
#define OFF_FFNHP  (16*MF)
#define OFF_FFNO   (32*MF)

__device__ float g_arena[ARENA_FLOATS];

__device__ __forceinline__ uint32_t f2tf32(float x){
    uint32_t r; asm("cvt.rna.tf32.f32 %0, %1;" : "=r"(r) : "f"(x)); return r;
}
__device__ __forceinline__ float rnd_tf32(float x){ return __uint_as_float(f2tf32(x)); }

__device__ __forceinline__ uint32_t smem_u32(const void* p){
    uint32_t a;
    asm("{ .reg .u64 t; cvta.to.shared.u64 t, %1; cvt.u32.u64 %0, t; }" : "=r"(a) : "l"(p));
    return a;
}
__device__ __forceinline__ void cp16(uint32_t dst, const float* src){
    asm volatile("cp.async.cg.shared.global [%0], [%1], 16;"
                 :: "r"(dst), "l"(src) : "memory");
}
__device__ __forceinline__ void mma_tf32(float* d, const uint32_t* a, const uint32_t* b){
    asm volatile("mma.sync.aligned.m16n8k8.row.col.f32.tf32.tf32.f32 "
                 "{%0,%1,%2,%3}, {%4,%5,%6,%7}, {%8,%9}, {%0,%1,%2,%3};"
                 : "+f"(d[0]), "+f"(d[1]), "+f"(d[2]), "+f"(d[3])
                 : "r"(a[0]), "r"(a[1]), "r"(a[2]), "r"(a[3]),
                   "r"(b[0]), "r"(b[1]));
}

/* permuted A-layout offset for element (m,k); nK8 = K/8.
   word order per lane: w0=(g,tig) w1=(g+8,tig) w2=(g,tig+4) w3=(g+8,tig+4) */
__device__ __forceinline__ size_t perm_off(int m, int k, int nK8){
    int mt = m>>7, mr = m&127;
    int fb = mr>>4, r16 = mr&15;
    int kc = k>>3, kr = k&7;
    return ((size_t)(mt*nK8 + kc)*8 + fb)*128
         + (size_t)((((r16&7)<<2) + (kr&3))<<2) + (r16>>3) + ((kr>>2)<<1);
}

/* ---------------- epilogues ---------------- */
template<int EPI, int RND>
__device__ __forceinline__ float epi_apply(float v, const float* __restrict__ bias, int n){
    float x = v;
    if (EPI != 0){
        x = v + bias[n];
        if (EPI == 2) x = 0.5f * x * (1.0f + erff(x * 0.70710678118654752f)); /* exact gelu */
        else if (EPI == 3) x = (x > 20.0f) ? x : log1pf(__expf(x));           /* softplus */
    }
    return RND ? rnd_tf32(x) : x;
}

/* ---------------- permute kernels (inputs -> fragment-ordered tf32) ---------------- */
/* B layout: ((ntile*nK8+kc)*16 + jb)*64 + (g*4+tig)*2 + w ; element: n=ntile*128+jb*8+g,
   k=kc*8+w*4+tig.  Index bit fields: w=bit0, lane=bits1-5, jb=bits6-9, blk=bits10+. */
__global__ __launch_bounds__(256) void permB(const float* __restrict__ src,
                                             float* __restrict__ dst,
                                             int N, int K, int total){
    int idx = blockIdx.x*256 + threadIdx.x;
    if (idx >= total) return;
    int w = idx & 1, lane = (idx>>1)&31, jb = (idx>>6)&15;
    int blk = idx>>10;
    int nK8 = K>>3;
    int kc = blk % nK8, ntile = blk / nK8;
    int n = ntile*128 + jb*8 + (lane>>2);
    int k = kc*8 + w*4 + (lane&3);
    dst[idx] = (n < N) ? rnd_tf32(src[(size_t)n*K + k]) : 0.f;
}
/* A layout: ((mt*nK8+kc)*8 + fb)*128 + (g*4+tig)*4 + w
   bit fields: w=bits0-1, lane=bits2-6, fb=bits7-9, blk=bits10+ */
__global__ __launch_bounds__(256) void permA(const float* __restrict__ src,
                                             float* __restrict__ dst,
                                             int lda, int K, int total){
    int idx = blockIdx.x*256 + threadIdx.x;
    if (idx >= total) return;
    int w = idx & 3, lane = (idx>>2)&31, fb = (idx>>7)&7;
    int blk = idx>>10;
    int nK8 = K>>3;
    int kc = blk % nK8, mt = blk / nK8;
    int m = mt*128 + fb*16 + (w&1)*8 + (lane>>2);
    int k = kc*8 + (w>>1)*4 + (lane&3);
    dst[idx] = rnd_tf32(src[(size_t)m*lda + k]);
}

/* ---------------- TF32 HMMA GEMM v4 on pre-permuted operands ----------------
   C[m,n] = sum_k A[m,k]*W[n,k].  CTA 128x128, 4 warps (warp tile 64x64, 4x8 frags).
   K-chunks of 32: cp.async identity copy of 16KB A + 16KB B, 3-stage, wait_group 1
   (two copies in flight -> copy latency hidden under compute).
   OUTP=1: store C permuted (A-layout for the NEXT gemm, Kdim nK8o). */
#define MM_SMEM 98304   /* 3 stages x (16KB A + 16KB B) */

template<int EPI, int RND, int OUTP>
__global__ __launch_bounds__(128) void mm_perm(
    const float* __restrict__ A0, const float* __restrict__ A1,
    const float* __restrict__ B0, const float* __restrict__ B1,
    const float* __restrict__ bias0, const float* __restrict__ bias1,
    float* __restrict__ C0, float* __restrict__ C1, int ldc,
    int N, int K, int nK8o)
{
    extern __shared__ float smem[];   /* [A: 3x4096][B: 3x4096] floats */
    const float* A    = blockIdx.z ? A1 : A0;
    const float* B    = blockIdx.z ? B1 : B0;
    const float* bias = blockIdx.z ? bias1 : bias0;
    float*       C    = blockIdx.z ? C1 : C0;

    int tid = threadIdx.x, wid = tid>>5, lane = tid&31;
    int wm = wid & 1, wn = wid >> 1;
    int g = lane>>2, tig = lane&3;
    int nK8 = K>>3;
    int KC  = K>>5;

    const float* Ach = A + ((size_t)blockIdx.y * nK8) * 1024;
    const float* Bch = B + ((size_t)blockIdx.x * nK8) * 1024;

    uint32_t sbase = smem_u32(smem);
    uint32_t sa_d = sbase + tid*128;             /* + stage*16384 */
    uint32_t sb_d = sbase + 49152 + tid*128;     /* B base = 3*16384 bytes */

    float acc[4][8][4];
    #pragma unroll
    for (int f=0;f<4;f++)
        #pragma unroll
        for (int j=0;j<8;j++)
            #pragma unroll
            for (int q=0;q<4;q++) acc[f][j][q] = 0.f;

    /* prologue: chunks 0,1 -> stages 0,1 (always commit to keep group count aligned) */
    #pragma unroll
    for (int s=0;s<2;s++){
        if (s < KC){
            const float* ag = Ach + (size_t)s*4096;
            const float* bg = Bch + (size_t)s*4096;
            uint32_t da = sa_d + s*16384;
            uint32_t db = sb_d + s*16384;
            #pragma unroll
            for (int q=0;q<8;q++){
                cp16(da + q*16, ag + tid*32 + q*4);
                cp16(db + q*16, bg + tid*32 + q*4);
            }
        }
        asm volatile("cp.async.commit_group;" ::: "memory");
    }

    for (int c=0;c<KC;c++){
        asm volatile("cp.async.wait_group 1;" ::: "memory");
        __syncthreads();
        if (c+2 < KC){
            int st = (c+2)%3;
            const float* ag = Ach + (size_t)(c+2)*4096;
            const float* bg = Bch + (size_t)(c+2)*4096;
            uint32_t da = sa_d + st*16384;
            uint32_t db = sb_d + st*16384;
            #pragma unroll
            for (int q=0;q<8;q++){
                cp16(da + q*16, ag + tid*32 + q*4);
                cp16(db + q*16, bg + tid*32 + q*4);
            }
        }
        asm volatile("cp.async.commit_group;" ::: "memory");

        const float* sAs = smem + (c%3)*4096;
        const float* sBs = smem + 12288 + (c%3)*4096;
        #pragma unroll
        for (int s=0;s<4;s++){
            uint32_t af[4][4], bf[8][2];
            #pragma unroll
            for (int f=0;f<4;f++)
                *(uint4*)af[f] = *(const uint4*)&sAs[s*1024 + (wm*4+f)*128 + lane*4];
            #pragma unroll
            for (int j=0;j<8;j++)
                *(uint2*)bf[j] = *(const uint2*)&sBs[s*1024 + (wn*8+j)*64 + lane*2];
            #pragma unroll
            for (int f=0;f<4;f++)
                #pragma unroll
                for (int j=0;j<8;j++)
                    mma_tf32(acc[f][j], af[f], bf[j]);
        }
    }

    /* epilogue */
    #pragma unroll
    for (int f=0;f<4;f++){
        int row = blockIdx.y*128 + wm*64 + f*16 + g;
        #pragma unroll
        for (int j=0;j<8;j++){
            int nb = blockIdx.x*128 + wn*64 + j*8;
            int cn = nb + tig*2;
            if (!OUTP){
                if (nb < N){
                    float2 v;
                    v.x = epi_apply<EPI,RND>(acc[f][j][0], bias, cn);
                    v.y = epi_apply<EPI,RND>(acc[f][j][1], bias, cn+1);
                    *(float2*)&C[(size_t)row * ldc + cn] = v;
                    v.x = epi_apply<EPI,RND>(acc[f][j][2], bias, cn);
                    v.y = epi_apply<EPI,RND>(acc[f][j][3], bias, cn+1);
                    *(float2*)&C[(size_t)(row+8) * ldc + cn] = v;
                }
            } else {
                #pragma unroll
                for (int q=0;q<4;q++){
                    int m = row + (q>>1)*8;
                    int k = cn + (q&1);
                    C[perm_off(m, k, nK8o)] = epi_apply<EPI,RND>(acc[f][j][q], bias, k);
                }
            }
        }
    }
}

/* ---------------- conv + SiLU: writes xc (row-major, scan) AND xcp (permuted) ---- */
__global__ __launch_bounds__(256) void conv_silu(
    const float* __restrict__ xzf, const float* __restrict__ xzb,
    const float* __restrict__ fw, const float* __restrict__ fbias,
    const float* __restrict__ bw, const float* __restrict__ bbias,
    float* __restrict__ xcf, float* __restrict__ xcb,
    float* __restrict__ xcpf, float* __restrict__ xcpb)
{
    int lin = blockIdx.x * 256 + threadIdx.x;
    int ch = lin & (DI-1);
    int t  = lin >> 10;
    int b  = blockIdx.y;
    int dir = blockIdx.z;
    const float* __restrict__ xin = dir ? xzb : xzf;
    const float* __restrict__ cw  = dir ? bw : fw;
    const float* __restrict__ cb  = dir ? bbias : fbias;
    float* out  = dir ? xcb : xcf;
    float* outp = dir ? xcpb : xcpf;

    float acc = __ldg(&cb[ch]);
    float w0 = __ldg(&cw[ch*4+0]), w1 = __ldg(&cw[ch*4+1]);
    float w2 = __ldg(&cw[ch*4+2]), w3 = __ldg(&cw[ch*4+3]);
    size_t base = ((size_t)b * LSEQ) * (2*DI) + ch;
    if (dir == 0){
        if (t-3 >= 0) acc = fmaf(w0, __ldg(&xin[base + (size_t)(t-3)*(2*DI)]), acc);
        if (t-2 >= 0) acc = fmaf(w1, __ldg(&xin[base + (size_t)(t-2)*(2*DI)]), acc);
        if (t-1 >= 0) acc = fmaf(w2, __ldg(&xin[base + (size_t)(t-1)*(2*DI)]), acc);
        acc = fmaf(w3, __ldg(&xin[base + (size_t)t*(2*DI)]), acc);
    } else {
        if (t+3 < LSEQ) acc = fmaf(w0, __ldg(&xin[base + (size_t)(t+3)*(2*DI)]), acc);
        if (t+2 < LSEQ) acc = fmaf(w1, __ldg(&xin[base + (size_t)(t+2)*(2*DI)]), acc);
        if (t+1 < LSEQ) acc = fmaf(w2, __ldg(&xin[base + (size_t)(t+1)*(2*DI)]), acc);
        acc = fmaf(w3, __ldg(&xin[base + (size_t)t*(2*DI)]), acc);
    }
    float v = rnd_tf32(acc / (1.0f + __expf(-acc)));
    int m = b*LSEQ + t;
    out[(size_t)m*DI + ch] = v;
    outp[perm_off(m, ch, DI/8)] = v;
}

/* ---------------- selective scan + gating: writes ygp (permuted only) ---------- */
__global__ __launch_bounds__(128) void scan_gate(
    const float* __restrict__ delta_f, const float* __restrict__ delta_b,
    const float* __restrict__ xc_f,    const float* __restrict__ xc_b,
    const float* __restrict__ xdbl_f,  const float* __restrict__ xdbl_b,
    const float* __restrict__ xz_f,    const float* __restrict__ xz_b,
    const float* __restrict__ Alog_f,  const float* __restrict__ Alog_b,
    const float* __restrict__ D_f,     const float* __restrict__ D_b,
    float* __restrict__ ygp_f, float* __restrict__ ygp_b)
{
    int dir = blockIdx.z;
    const float* __restrict__ delta = dir ? delta_b : delta_f;
    const float* __restrict__ xc    = dir ? xc_b    : xc_f;
    const float* __restrict__ xdbl  = dir ? xdbl_b  : xdbl_f;
    const float* __restrict__ xz    = dir ? xz_b    : xz_f;
    const float* __restrict__ Alog  = dir ? Alog_b  : Alog_f;
    const float* __restrict__ Dp    = dir ? D_b     : D_f;
    float* ygp                      = dir ? ygp_b   : ygp_f;

    int ch = blockIdx.x * 128 + threadIdx.x;
    int b  = blockIdx.y;

    float Aev[32];
    #pragma unroll
    for (int n=0;n<32;n++) Aev[n] = -__expf(__ldg(&Alog[ch*32 + n]));
    float Dch = __ldg(&Dp[ch]);
    float h[32];
    #pragma unroll
    for (int n=0;n<32;n++) h[n] = 0.f;

    /* permuted-write constants for this channel (K=DI, nK8=128) */
    int kc = ch>>3;
    int tg = ch&3;
    int chb = ((ch>>2)&1)<<1;

    int t0 = dir ? (LSEQ-1) : 0;
    size_t row0 = (size_t)b*LSEQ + t0;
    float d  = __ldg(&delta[row0*DI + ch]);
    float u  = __ldg(&xc[row0*DI + ch]);
    float zz = __ldg(&xz[row0*(2*DI) + DI + ch]);

    for (int s=0;s<LSEQ;s++){
        int t = dir ? (LSEQ-1 - s) : s;
        /* L1 prefetch of the B/C row two timesteps ahead (row spans 256B) */
        if (s+2 < LSEQ){
            int tp = dir ? (t-2) : (t+2);
            const float* pf = xdbl + ((size_t)b*LSEQ + tp)*96 + 32;
            asm volatile("prefetch.global.L1 [%0];" :: "l"(pf));
            asm volatile("prefetch.global.L1 [%0];" :: "l"(pf+32));
            asm volatile("prefetch.global.L1 [%0];" :: "l"(pf+63));
        }
        float dn=0.f, un=0.f, zn=0.f;
        if (s+1 < LSEQ){
            int tn = dir ? (t-1) : (t+1);
            size_t rn = (size_t)b*LSEQ + tn;
            dn = __ldg(&delta[rn*DI + ch]);
            un = __ldg(&xc[rn*DI + ch]);
            zn = __ldg(&xz[rn*(2*DI) + DI + ch]);
        }
        size_t row = (size_t)b*LSEQ + t;
        const float4* Bp = (const float4*)(xdbl + row*96 + 32);
        const float4* Cp = (const float4*)(xdbl + row*96 + 64);
        float du = d * u;
        float y = 0.f;
        #pragma unroll
        for (int q=0;q<8;q++){
            float4 B4 = __ldg(&Bp[q]);
            float4 C4 = __ldg(&Cp[q]);
            int n = q*4;
            float dA;
            dA = __expf(d*Aev[n+0]); h[n+0] = fmaf(dA, h[n+0], du*B4.x); y = fmaf(h[n+0], C4.x, y);
            dA = __expf(d*Aev[n+1]); h[n+1] = fmaf(dA, h[n+1], du*B4.y); y = fmaf(h[n+1], C4.y, y);
            dA = __expf(d*Aev[n+2]); h[n+2] = fmaf(dA, h[n+2], du*B4.z); y = fmaf(h[n+2], C4.z, y);
            dA = __expf(d*Aev[n+3]); h[n+3] = fmaf(dA, h[n+3], du*B4.w); y = fmaf(h[n+3], C4.w, y);
        }
        float yv = fmaf(u, Dch, y);
        float sz = zz / (1.0f + __expf(-zz));
        /* permuted store: m = b*LSEQ+t ; mr = t&127 ; mt = b*8 + (t>>7) */
        int mr = t & 127;
        int mt = (b<<3) + (t>>7);
        size_t poff = ((size_t)(mt*128 + kc)*8 + (mr>>4))*128
                    + (size_t)((((mr&7)<<2) + tg)<<2) + ((mr>>3)&1) + chb;
        ygp[poff] = rnd_tf32(yv * sz);
        d = dn; u = un; zz = zn;
    }
}

/* ---------------- layernorm helpers ---------------- */
__device__ __forceinline__ float block_sum128(float v, float* sh){
    #pragma unroll
    for (int o=16;o>0;o>>=1) v += __shfl_xor_sync(0xffffffffu, v, o);
    if ((threadIdx.x & 31) == 0) sh[threadIdx.x >> 5] = v;
    __syncthreads();
    float r = sh[0] + sh[1] + sh[2] + sh[3];
    __syncthreads();
    return r;
}

/* out1 = LN(hf*pw0 + hb*pw1 + pb + x): writes row-major (residual) + permuted (FFN A) */
__global__ __launch_bounds__(128) void combine_ln(
    const float* __restrict__ of, const float* __restrict__ ob, const float* __restrict__ x,
    const float* __restrict__ pw, const float* __restrict__ pb,
    const float* __restrict__ g, const float* __restrict__ be,
    float* __restrict__ out, float* __restrict__ outp)
{
    __shared__ float sh[4];
    size_t m = blockIdx.x;
    float w0 = __ldg(&pw[0]), w1 = __ldg(&pw[1]), b0 = __ldg(&pb[0]);
    float v[4]; float s = 0.f;
    #pragma unroll
    for (int i=0;i<4;i++){
        int n = threadIdx.x + i*128;
        size_t idx = m*DM + n;
        float val = fmaf(of[idx], w0, fmaf(ob[idx], w1, b0 + x[idx]));
        v[i] = val; s += val;
    }
    float mu = block_sum128(s, sh) * (1.f/(float)DM);
    float s2 = 0.f;
    #pragma unroll
    for (int i=0;i<4;i++){ float dd = v[i]-mu; s2 = fmaf(dd,dd,s2); }
    float inv = rsqrtf(block_sum128(s2, sh)*(1.f/(float)DM) + 1e-12f);
    #pragma unroll
    for (int i=0;i<4;i++){
        int n = threadIdx.x + i*128;
        float val = rnd_tf32(fmaf((v[i]-mu)*inv, g[n], be[n]));
        out[m*DM + n] = val;
        outp[perm_off((int)m, n, DM/8)] = val;
    }
}

__global__ __launch_bounds__(128) void add_ln(
    const float* __restrict__ a, const float* __restrict__ r,
    const float* __restrict__ g, const float* __restrict__ be, float* __restrict__ out)
{
    __shared__ float sh[4];
    size_t m = blockIdx.x;
    float v[4]; float s = 0.f;
    #pragma unroll
    for (int i=0;i<4;i++){
        int n = threadIdx.x + i*128;
        size_t idx = m*DM + n;
        float val = a[idx] + r[idx];
        v[i] = val; s += val;
    }
    float mu = block_sum128(s, sh) * (1.f/(float)DM);
    float s2 = 0.f;
    #pragma unroll
    for (int i=0;i<4;i++){ float dd = v[i]-mu; s2 = fmaf(dd,dd,s2); }
    float inv = rsqrtf(block_sum128(s2, sh)*(1.f/(float)DM) + 1e-12f);
    #pragma unroll
    for (int i=0;i<4;i++){
        int n = threadIdx.x + i*128;
        out[m*DM + n] = fmaf((v[i]-mu)*inv, g[n], be[n]);
    }
}

/* ---------------- eager init ---------------- */
namespace {
struct EagerInit {
    float* base;
    EagerInit() : base(nullptr) {
        void* p = nullptr;
        cudaGetSymbolAddress(&p, g_arena);
        base = (float*)p;
        cudaFuncSetAttribute(mm_perm<0,0,0>, cudaFuncAttributeMaxDynamicSharedMemorySize, MM_SMEM);
        cudaFuncSetAttribute(mm_perm<0,1,0>, cudaFuncAttributeMaxDynamicSharedMemorySize, MM_SMEM);
        cudaFuncSetAttribute(mm_perm<3,0,0>, cudaFuncAttributeMaxDynamicSharedMemorySize, MM_SMEM);
        cudaFuncSetAttribute(mm_perm<2,1,1>, cudaFuncAttributeMaxDynamicSharedMemorySize, MM_SMEM);
        cudaFuncSetAttribute(mm_perm<1,0,0>, cudaFuncAttributeMaxDynamicSharedMemorySize, MM_SMEM);
    }
};
EagerInit g_eager;
}

/* ---------------- host helpers ---------------- */
static inline void runPermB(const float* s, float* d, int N, int K){
    int total = ((N+127)/128) * (K/8) * 1024;
    permB<<<(total+255)/256, 256>>>(s, d, N, K, total);
}
static inline void runPermA(const float* s, float* d, int lda, int K){
    int total = (MROWS/128) * (K/8) * 1024;
    permA<<<(total+255)/256, 256>>>(s, d, lda, K, total);
}

extern "C" void kernel_launch(void* const* d_in, const int* in_sizes, int n_in,
                              void* d_out, int out_size)
{
    const float* X        = (const float*)d_in[0];
    /* d_in[1] = lengths (unused by the reference) */
    const float* f_in_w   = (const float*)d_in[2];
    const float* f_conv_w = (const float*)d_in[3];
    const float* f_conv_b = (const float*)d_in[4];
    const float* f_xproj  = (const float*)d_in[5];
    const float* f_dt_w   = (const float*)d_in[6];
    const float* f_dt_b   = (const float*)d_in[7];
    const float* f_A_log  = (const float*)d_in[8];
    const float* f_D      = (const float*)d_in[9];
    const float* f_out_w  = (const float*)d_in[10];
    const float* b_in_w   = (const float*)d_in[11];
    const float* b_conv_w = (const float*)d_in[12];
    const float* b_conv_b = (const float*)d_in[13];
    const float* b_xproj  = (const float*)d_in[14];
    const float* b_dt_w   = (const float*)d_in[15];
    const float* b_dt_b   = (const float*)d_in[16];
    const float* b_A_log  = (const float*)d_in[17];
    const float* b_D      = (const float*)d_in[18];
    const float* b_out_w  = (const float*)d_in[19];
    const float* proj_w   = (const float*)d_in[20];
    const float* proj_b   = (const float*)d_in[21];
    const float* ln_g     = (const float*)d_in[22];
    const float* ln_b     = (const float*)d_in[23];
    const float* ffn_w1   = (const float*)d_in[24];
    const float* ffn_b1   = (const float*)d_in[25];
    const float* ffn_w2   = (const float*)d_in[26];
    const float* ffn_b2   = (const float*)d_in[27];
    const float* ffn_ln_g = (const float*)d_in[28];
    const float* ffn_ln_b = (const float*)d_in[29];

    float* base = g_eager.base;
    if (!base){ void* p = nullptr; cudaGetSymbolAddress(&p, g_arena); base = (float*)p; }

    float* xz_f   = base + OFF_XZ_F;
    float* xz_b   = base + OFF_XZ_B;
    float* xc_f   = base + OFF_XC_F;
    float* xc_b   = base + OFF_XC_B;
    float* dlt_f  = base + OFF_DLT_F;
    float* dlt_b  = base + OFF_DLT_B;
    float* xdbl_f = base + OFF_XDBL_F;
    float* xdbl_b = base + OFF_XDBL_B;
    float* out_f  = base + OFF_OUT_F;
    float* out_b  = base + OFF_OUT_B;
    float* out1   = base + OFF_OUT1;
    float* ffno   = base + OFF_FFNO;
    float* Xp     = base + OFF_XP;
    float* xcp_f  = base + OFF_XCP_F;
    float* xcp_b  = base + OFF_XCP_B;
    float* ygp_f  = base + OFF_YGP_F;
    float* ygp_b  = base + OFF_YGP_B;
    float* out1p  = base + OFF_OUT1P;
    float* ffnhp  = base + OFF_FFNHP;
    float* dtap_f = base + OFF_DTAP_F;
    float* dtap_b = base + OFF_DTAP_B;
    float* fiwP   = base + OFF_FIWP;
    float* biwP   = base + OFF_BIWP;
    float* fxpP   = base + OFF_FXPP;
    float* bxpP   = base + OFF_BXPP;
    float* fdtP   = base + OFF_FDTP;
    float* bdtP   = base + OFF_BDTP;
    float* fowP   = base + OFF_FOWP;
    float* bowP   = base + OFF_BOWP;
    float* w1P    = base + OFF_W1P;
    float* w2P    = base + OFF_W2P;
    float* OUT    = (float*)d_out;

    /* 0a) GEMM1's inputs only (3 launches) so GEMM1 is launch index 3 -> ncu capture */
    runPermB(f_in_w, fiwP, 2*DI, DM);    /* idx 0 */
    runPermB(b_in_w, biwP, 2*DI, DM);    /* idx 1 */
    runPermA(X, Xp, DM, DM);             /* idx 2 */

    /* 1) in_proj both dirs: xz = X @ in_w^T  (N=2048, K=512)  -- launch index 3 */
    mm_perm<0,0,0><<<dim3(16,64,2),128,MM_SMEM>>>(Xp, Xp, fiwP, biwP,
                                                  nullptr, nullptr, xz_f, xz_b, 2*DI,
                                                  2*DI, DM, 0);

    /* 0b) remaining weight permutes (independent of GEMM1) */
    runPermB(f_xproj, fxpP, 96, DI);    runPermB(b_xproj, bxpP, 96, DI);
    runPermB(f_dt_w, fdtP, DI, 32);     runPermB(b_dt_w, bdtP, DI, 32);
    runPermB(f_out_w, fowP, DM, DI);    runPermB(b_out_w, bowP, DM, DI);
    runPermB(ffn_w1, w1P, 4*DM, DM);    runPermB(ffn_w2, w2P, DM, 4*DM);

    /* 2) depthwise conv + silu: xc row-major + permuted */
    conv_silu<<<dim3((LSEQ*DI)/256, BSZ, 2),256>>>(xz_f, xz_b,
                                                   f_conv_w, f_conv_b, b_conv_w, b_conv_b,
                                                   xc_f, xc_b, xcp_f, xcp_b);

    /* 3) x_dbl = xc @ xproj^T  (N=96 padded 128, K=1024), rounded out */
    mm_perm<0,1,0><<<dim3(1,64,2),128,MM_SMEM>>>(xcp_f, xcp_b, fxpP, bxpP,
                                                 nullptr, nullptr, xdbl_f, xdbl_b, 96,
                                                 96, DI, 0);

    /* 3b) dt-part of xdbl -> permuted A for GEMM4 (overlays dead Xp) */
    runPermA(xdbl_f, dtap_f, 96, 32);
    runPermA(xdbl_b, dtap_b, 96, 32);

    /* 4) delta = softplus(dt @ dt_w^T + dt_b)  (N=1024, K=32) */
    mm_perm<3,0,0><<<dim3(8,64,2),128,MM_SMEM>>>(dtap_f, dtap_b, fdtP, bdtP,
                                                 f_dt_b, b_dt_b, dlt_f, dlt_b, DI,
                                                 DI, 32, 0);

    /* 5) selective scan + u*D + silu(z) gate -> ygp (overlays dead xcp) */
    scan_gate<<<dim3(DI/128, BSZ, 2),128>>>(dlt_f, dlt_b, xc_f, xc_b,
                                            xdbl_f, xdbl_b, xz_f, xz_b,
                                            f_A_log, b_A_log, f_D, b_D,
                                            ygp_f, ygp_b);

    /* 6) out_proj: yg @ out_w^T  (N=512, K=1024); out_f/out_b overlay dead xz head */
    mm_perm<0,0,0><<<dim3(4,64,2),128,MM_SMEM>>>(ygp_f, ygp_b, fowP, bowP,
                                                 nullptr, nullptr, out_f, out_b, DM,
                                                 DM, DI, 0);

    /* 7) out1 = LN(hf*pw0 + hb*pw1 + pb + x): row-major + permuted */
    combine_ln<<<MROWS,128>>>(out_f, out_b, X, proj_w, proj_b, ln_g, ln_b,
                              out1, out1p);

    /* 8) FFN up + gelu -> ffnhp permuted (Kout=2048)  (N=2048, K=512) */
    mm_perm<2,1,1><<<dim3(16,64,1),128,MM_SMEM>>>(out1p, out1p, w1P, w1P,
                                                  ffn_b1, ffn_b1, ffnhp, ffnhp, 0,
                                                  4*DM, DM, (4*DM)/8);

    /* 9) FFN down + bias  (N=512, K=2048) */
    mm_perm<1,0,0><<<dim3(4,64,1),128,MM_SMEM>>>(ffnhp, ffnhp, w2P, w2P,
                                                 ffn_b2, ffn_b2, ffno, ffno, DM,
                                                 DM, 4*DM, 0);

    /* 10) final = LN(ffn_out + out1) */
    add_ln<<<MROWS,128>>>(ffno, out1, ffn_ln_g, ffn_ln_b, OUT);
}